// round 2
// baseline (speedup 1.0000x reference)
#include <cuda_runtime.h>
#include <math.h>
#include <float.h>
#include <limits.h>

// Problem constants
#define Bb 2
#define Tt 2048
#define Dd 1024
#define Nn 16
#define Kk 8
#define Hh 128
#define Gg 2
#define Mrows (Bb*Tt)          // 4096

__device__ __constant__ float c_dummy; // keep nvcc happy about empty constant use

static constexpr float EPSf   = 1e-6f;
static constexpr float LOG_THETA = 13.815510557964274f;  // ln(1e6)
static constexpr float SCALEf = 0.08838834764831845f;    // 128^-0.5

// Scratch (allocation-free rule: __device__ globals)
__device__ float g_q[(size_t)Mrows * Nn * Hh];   // 32 MB
__device__ float g_k[(size_t)Mrows * Kk * Hh];   // 16 MB
__device__ float g_v[(size_t)Mrows * Kk * Hh];   // 16 MB
__device__ float g_att[(size_t)Mrows * Nn * Hh]; // 32 MB
__device__ int   g_pos[Mrows];

// ---------------------------------------------------------------------------
// positions_from_segment_ids: off = argmax(seg) (first occurrence), rel = t-off
// ---------------------------------------------------------------------------
__global__ void pos_kernel(const int* __restrict__ seg) {
    int b = blockIdx.x;
    int tid = threadIdx.x;
    __shared__ int sv[256], si[256];
    int bv = INT_MIN, bi = INT_MAX;
    for (int t = tid; t < Tt; t += 256) {
        int v = seg[b * Tt + t];
        if (v > bv) { bv = v; bi = t; }
    }
    sv[tid] = bv; si[tid] = bi;
    __syncthreads();
    for (int o = 128; o; o >>= 1) {
        if (tid < o) {
            if (sv[tid + o] > sv[tid] ||
                (sv[tid + o] == sv[tid] && si[tid + o] < si[tid])) {
                sv[tid] = sv[tid + o]; si[tid] = si[tid + o];
            }
        }
        __syncthreads();
    }
    int off = si[0];
    for (int t = tid; t < Tt; t += 256) {
        int v = seg[b * Tt + t];
        g_pos[b * Tt + t] = (v != 0) ? (t - off) : (1 << 30);
    }
}

// ---------------------------------------------------------------------------
// Generic fp32 SGEMM: C[M,Nc] = A[M,Kd] * B[Kd,Nc], all row-major.
// 128x128 block tile, BK=8, 256 threads, 8x8 per thread.
// Requires M,Nc % 128 == 0, Kd % 8 == 0 (true for all our shapes).
// ---------------------------------------------------------------------------
__global__ __launch_bounds__(256)
void sgemm128(const float* __restrict__ A, const float* __restrict__ B,
              float* __restrict__ C, int M, int Nc, int Kd) {
    __shared__ float As[8][128];
    __shared__ float Bs[8][128];
    const int tid = threadIdx.x;
    const int m0 = blockIdx.y * 128;
    const int n0 = blockIdx.x * 128;
    const int ty = tid >> 4, tx = tid & 15;

    const int a_row = tid >> 1;            // 0..127
    const int a_k   = (tid & 1) * 4;       // 0 or 4
    const int b_k   = tid >> 5;            // 0..7
    const int b_col = (tid & 31) * 4;      // 0..124

    float acc[8][8];
#pragma unroll
    for (int i = 0; i < 8; i++)
#pragma unroll
        for (int j = 0; j < 8; j++) acc[i][j] = 0.f;

    for (int k0 = 0; k0 < Kd; k0 += 8) {
        float4 av = *(const float4*)&A[(size_t)(m0 + a_row) * Kd + k0 + a_k];
        As[a_k + 0][a_row] = av.x;
        As[a_k + 1][a_row] = av.y;
        As[a_k + 2][a_row] = av.z;
        As[a_k + 3][a_row] = av.w;
        float4 bv = *(const float4*)&B[(size_t)(k0 + b_k) * Nc + n0 + b_col];
        *(float4*)&Bs[b_k][b_col] = bv;
        __syncthreads();
#pragma unroll
        for (int kk = 0; kk < 8; kk++) {
            float a[8], b[8];
#pragma unroll
            for (int i = 0; i < 8; i++) a[i] = As[kk][ty * 8 + i];
#pragma unroll
            for (int j = 0; j < 8; j++) b[j] = Bs[kk][tx * 8 + j];
#pragma unroll
            for (int i = 0; i < 8; i++)
#pragma unroll
                for (int j = 0; j < 8; j++) acc[i][j] += a[i] * b[j];
        }
        __syncthreads();
    }
#pragma unroll
    for (int i = 0; i < 8; i++) {
#pragma unroll
        for (int j = 0; j < 8; j += 4) {
            float4 o = make_float4(acc[i][j], acc[i][j + 1], acc[i][j + 2], acc[i][j + 3]);
            *(float4*)&C[(size_t)(m0 + ty * 8 + i) * Nc + n0 + tx * 8 + j] = o;
        }
    }
}

// ---------------------------------------------------------------------------
// Fused RMSNorm + RoPE over rows of H=128.
// buf layout: [(b*T+t)*heads + n][128]
// ---------------------------------------------------------------------------
__global__ __launch_bounds__(128)
void norm_rope_kernel(float* __restrict__ buf, const float* __restrict__ scale,
                      int heads) {
    const int row  = blockIdx.x;
    const int h    = threadIdx.x;
    const int trow = row / heads;              // b*T + t

    float v = buf[(size_t)row * Hh + h];
    float ss = v * v;
#pragma unroll
    for (int o = 16; o; o >>= 1) ss += __shfl_xor_sync(0xffffffffu, ss, o);
    __shared__ float warpsum[4];
    __shared__ float s_n[Hh];
    if ((h & 31) == 0) warpsum[h >> 5] = ss;
    __syncthreads();
    float total = warpsum[0] + warpsum[1] + warpsum[2] + warpsum[3];
    float inv_rms = rsqrtf(total * (1.0f / 128.0f) + EPSf);
    s_n[h] = v * inv_rms * scale[h];
    __syncthreads();

    int pos = g_pos[trow];
    int i = h & 63;
    float inv_freq = __expf(-(float)i * (LOG_THETA / 64.0f));
    float ang = (float)pos * inv_freq;
    float sn = sinf(ang), cs = cosf(ang);
    float out = (h < 64) ? (s_n[h] * cs - s_n[h + 64] * sn)
                         : (s_n[h] * cs + s_n[h - 64] * sn);
    buf[(size_t)row * Hh + h] = out;
}

// ---------------------------------------------------------------------------
// Flash attention, fp32, 64-query x 64-key tiles, online softmax.
// grid = (T/64, N, B); block = 256.
// ---------------------------------------------------------------------------
#define QT 64
#define KT 64
#define QPAD 129
#define SPAD 65

__global__ __launch_bounds__(256)
void attn_kernel(const int* __restrict__ seg) {
    extern __shared__ char sm_raw[];
    float* sQ = (float*)sm_raw;               // 64*129
    float* sK = sQ + QT * QPAD;               // 64*129
    float* sV = sK + KT * QPAD;               // 64*129
    float* sS = sV + KT * QPAD;               // 64*65
    float* sM = sS + QT * SPAD;               // 64
    float* sL = sM + QT;                      // 64
    float* sA = sL + QT;                      // 64 (alpha)
    int* sQpos = (int*)(sA + QT);             // 64
    int* sQseg = sQpos + QT;                  // 64
    int* sKpos = sQseg + QT;                  // 64
    int* sKseg = sKpos + KT;                  // 64
    int* sCtl  = sKseg + KT;                  // [0]=qmax, [1]=skip

    const int tid   = threadIdx.x;
    const int qbase = blockIdx.x * QT;
    const int n     = blockIdx.y;
    const int b     = blockIdx.z;
    const int kvh   = n / Gg;

    // Load Q tile (pre-scaled), positions, segment ids
    for (int idx = tid; idx < QT * Hh; idx += 256) {
        int qi = idx >> 7, h = idx & 127;
        sQ[qi * QPAD + h] =
            g_q[(((size_t)(b * Tt + qbase + qi)) * Nn + n) * Hh + h] * SCALEf;
    }
    if (tid < QT) {
        sQpos[tid] = g_pos[b * Tt + qbase + tid];
        sQseg[tid] = seg[b * Tt + qbase + tid];
        sM[tid] = -1e30f;
        sL[tid] = 0.f;
    }
    __syncthreads();
    if (tid == 0) {
        int mx = INT_MIN;
        for (int j = 0; j < QT; j++) mx = max(mx, sQpos[j]);
        sCtl[0] = mx;
    }
    __syncthreads();
    const int qmax = sCtl[0];

    const int ty = tid >> 4, tx = tid & 15;   // 16x16 for scores
    const int oq = tid >> 2, od = tid & 3;    // O-accum: row oq, dims od+4*j
    float acc[32];
#pragma unroll
    for (int j = 0; j < 32; j++) acc[j] = 0.f;

    for (int kt = 0; kt < Tt / KT; ++kt) {
        const int sbase = kt * KT;
        if (tid < KT) {
            sKpos[tid] = g_pos[b * Tt + sbase + tid];
            sKseg[tid] = seg[b * Tt + sbase + tid];
        }
        __syncthreads();
        if (tid == 0) {
            int kmin = INT_MAX;
            for (int j = 0; j < KT; j++) kmin = min(kmin, sKpos[j]);
            sCtl[1] = (kmin > qmax) ? 1 : 0;
        }
        __syncthreads();
        if (sCtl[1]) { __syncthreads(); continue; }

        // Load K,V tiles
        for (int idx = tid; idx < KT * Hh; idx += 256) {
            int s = idx >> 7, h = idx & 127;
            size_t base = (((size_t)(b * Tt + sbase + s)) * Kk + kvh) * Hh + h;
            sK[s * QPAD + h] = g_k[base];
            sV[s * QPAD + h] = g_v[base];
        }
        __syncthreads();

        // Scores: S = Q K^T (each thread 4x4)
        float as[4][4];
#pragma unroll
        for (int r = 0; r < 4; r++)
#pragma unroll
            for (int c = 0; c < 4; c++) as[r][c] = 0.f;
        for (int k = 0; k < Hh; k++) {
            float a[4], bv[4];
#pragma unroll
            for (int r = 0; r < 4; r++) a[r] = sQ[(ty * 4 + r) * QPAD + k];
#pragma unroll
            for (int c = 0; c < 4; c++) bv[c] = sK[(tx * 4 + c) * QPAD + k];
#pragma unroll
            for (int r = 0; r < 4; r++)
#pragma unroll
                for (int c = 0; c < 4; c++) as[r][c] += a[r] * bv[c];
        }
#pragma unroll
        for (int r = 0; r < 4; r++) {
#pragma unroll
            for (int c = 0; c < 4; c++) {
                int i = ty * 4 + r, j = tx * 4 + c;
                bool ok = (sKpos[j] <= sQpos[i]) && (sKseg[j] == sQseg[i]);
                sS[i * SPAD + j] = ok ? as[r][c] : -1e30f;
            }
        }
        __syncthreads();

        // Online softmax per row (threads 0..63)
        if (tid < QT) {
            int i = tid;
            float m_old = sM[i];
            float mx = -1e30f;
#pragma unroll 8
            for (int j = 0; j < KT; j++) mx = fmaxf(mx, sS[i * SPAD + j]);
            float new_m = fmaxf(m_old, mx);
            bool dead = (new_m < -0.9e30f);
            float alpha = dead ? 1.f : __expf(m_old - new_m);
            float lsum = 0.f;
#pragma unroll 8
            for (int j = 0; j < KT; j++) {
                float p = dead ? 0.f : __expf(sS[i * SPAD + j] - new_m);
                sS[i * SPAD + j] = p;
                lsum += p;
            }
            sL[i] = sL[i] * alpha + lsum;
            sM[i] = new_m;
            sA[i] = alpha;
        }
        __syncthreads();

        // O += P @ V  (rescale by alpha first)
        float alpha = sA[oq];
#pragma unroll
        for (int j = 0; j < 32; j++) acc[j] *= alpha;
        for (int s = 0; s < KT; s++) {
            float p = sS[oq * SPAD + s];
            const float* vr = &sV[s * QPAD + od];
#pragma unroll
            for (int j = 0; j < 32; j++) acc[j] += p * vr[4 * j];
        }
        __syncthreads();
    }

    float l = sL[oq];
    float inv_l = (l > 0.f) ? (1.f / l) : 0.f;
    size_t obase = (((size_t)(b * Tt + qbase + oq)) * Nn + n) * Hh + od;
#pragma unroll
    for (int j = 0; j < 32; j++) g_att[obase + 4 * j] = acc[j] * inv_l;
}

// ---------------------------------------------------------------------------
extern "C" void kernel_launch(void* const* d_in, const int* in_sizes, int n_in,
                              void* d_out, int out_size) {
    const float* x       = (const float*)d_in[0];
    const int*   seg     = (const int*)  d_in[1];
    const float* wq      = (const float*)d_in[2];
    const float* wk      = (const float*)d_in[3];
    const float* wv      = (const float*)d_in[4];
    const float* wo      = (const float*)d_in[5];
    const float* q_scale = (const float*)d_in[6];
    const float* k_scale = (const float*)d_in[7];
    float* out = (float*)d_out;

    float *qp, *kp, *vp, *ap;
    cudaGetSymbolAddress((void**)&qp, g_q);
    cudaGetSymbolAddress((void**)&kp, g_k);
    cudaGetSymbolAddress((void**)&vp, g_v);
    cudaGetSymbolAddress((void**)&ap, g_att);

    pos_kernel<<<Bb, 256>>>(seg);

    // QKV projections
    sgemm128<<<dim3(2048 / 128, Mrows / 128), 256>>>(x, wq, qp, Mrows, 2048, Dd);
    sgemm128<<<dim3(1024 / 128, Mrows / 128), 256>>>(x, wk, kp, Mrows, 1024, Dd);
    sgemm128<<<dim3(1024 / 128, Mrows / 128), 256>>>(x, wv, vp, Mrows, 1024, Dd);

    // RMSNorm + RoPE for q and k
    norm_rope_kernel<<<Mrows * Nn, 128>>>(qp, q_scale, Nn);
    norm_rope_kernel<<<Mrows * Kk, 128>>>(kp, k_scale, Kk);

    // Flash attention
    size_t smem_bytes =
        (size_t)(3 * QT * QPAD + QT * SPAD + 3 * QT) * sizeof(float) +
        (size_t)(4 * QT + 8) * sizeof(int);
    cudaFuncSetAttribute(attn_kernel, cudaFuncAttributeMaxDynamicSharedMemorySize,
                         (int)smem_bytes);
    attn_kernel<<<dim3(Tt / QT, Nn, Bb), 256, smem_bytes>>>(seg);

    // Output projection
    sgemm128<<<dim3(1024 / 128, Mrows / 128), 256>>>(ap, wo, out, Mrows, 1024, 2048);
}

// round 5
// speedup vs baseline: 1.2879x; 1.2879x over previous
#include <cuda_runtime.h>
#include <cuda_bf16.h>
#include <math.h>
#include <float.h>
#include <limits.h>
#include <stdint.h>

// Problem constants
#define Bb 2
#define Tt 2048
#define Dd 1024
#define Nn 16
#define Kk 8
#define Hh 128
#define Gg 2
#define Mrows (Bb*Tt)          // 4096

static constexpr float EPSf   = 1e-6f;
static constexpr float LOG_THETA = 13.815510557964274f;  // ln(1e6)
static constexpr float SCALEf = 0.08838834764831845f;    // 128^-0.5

// ---------------------------------------------------------------------------
// Scratch (allocation-free rule: __device__ globals)
// ---------------------------------------------------------------------------
__device__ float g_q[(size_t)Mrows * Nn * Hh];   // 32 MB
__device__ float g_k[(size_t)Mrows * Kk * Hh];   // 16 MB
__device__ float g_v[(size_t)Mrows * Kk * Hh];   // 16 MB
__device__ float g_att[(size_t)Mrows * Nn * Hh]; // 32 MB
__device__ int   g_pos[Mrows];

// bf16 split buffers
__device__ __nv_bfloat16 g_xhi[(size_t)Mrows * Dd];
__device__ __nv_bfloat16 g_xlo[(size_t)Mrows * Dd];
__device__ __nv_bfloat16 g_atthi[(size_t)Mrows * Nn * Hh];
__device__ __nv_bfloat16 g_attlo[(size_t)Mrows * Nn * Hh];
__device__ __nv_bfloat16 g_wqT_hi[(size_t)(Nn*Hh) * Dd];
__device__ __nv_bfloat16 g_wqT_lo[(size_t)(Nn*Hh) * Dd];
__device__ __nv_bfloat16 g_wkT_hi[(size_t)(Kk*Hh) * Dd];
__device__ __nv_bfloat16 g_wkT_lo[(size_t)(Kk*Hh) * Dd];
__device__ __nv_bfloat16 g_wvT_hi[(size_t)(Kk*Hh) * Dd];
__device__ __nv_bfloat16 g_wvT_lo[(size_t)(Kk*Hh) * Dd];
__device__ __nv_bfloat16 g_woT_hi[(size_t)Dd * (Nn*Hh)];
__device__ __nv_bfloat16 g_woT_lo[(size_t)Dd * (Nn*Hh)];

// ---------------------------------------------------------------------------
// PTX helpers (sm_103 baseline ISA only: cp.async, ldmatrix, mma.sync)
// ---------------------------------------------------------------------------
__device__ __forceinline__ uint32_t smem_u32(const void* p) {
    uint32_t a;
    asm("{ .reg .u64 t; cvta.to.shared.u64 t, %1; cvt.u32.u64 %0, t; }"
        : "=r"(a) : "l"(p));
    return a;
}
#define SW128(off) ((off) ^ (((off) >> 3) & 0x70))

#define CP_ASYNC16(saddr, gaddr) \
    asm volatile("cp.async.cg.shared.global [%0], [%1], 16;" \
        :: "r"(saddr), "l"(gaddr) : "memory")
#define CP_COMMIT() asm volatile("cp.async.commit_group;" ::: "memory")
#define CP_WAIT(n)  asm volatile("cp.async.wait_group %0;" :: "n"(n) : "memory")

#define LDSM_X4(r, addr) \
    asm volatile("ldmatrix.sync.aligned.m8n8.x4.shared.b16 {%0,%1,%2,%3}, [%4];" \
        : "=r"((r)[0]), "=r"((r)[1]), "=r"((r)[2]), "=r"((r)[3]) : "r"(addr))

#define MMA16816(d, a, b) \
    asm volatile("mma.sync.aligned.m16n8k16.row.col.f32.bf16.bf16.f32 " \
        "{%0,%1,%2,%3}, {%4,%5,%6,%7}, {%8,%9}, {%0,%1,%2,%3};" \
        : "+f"((d)[0]), "+f"((d)[1]), "+f"((d)[2]), "+f"((d)[3]) \
        : "r"((a)[0]), "r"((a)[1]), "r"((a)[2]), "r"((a)[3]), \
          "r"((b)[0]), "r"((b)[1]))

// ---------------------------------------------------------------------------
// positions_from_segment_ids
// ---------------------------------------------------------------------------
__global__ void pos_kernel(const int* __restrict__ seg) {
    int b = blockIdx.x;
    int tid = threadIdx.x;
    __shared__ int sv[256], si[256];
    int bv = INT_MIN, bi = INT_MAX;
    for (int t = tid; t < Tt; t += 256) {
        int v = seg[b * Tt + t];
        if (v > bv) { bv = v; bi = t; }
    }
    sv[tid] = bv; si[tid] = bi;
    __syncthreads();
    for (int o = 128; o; o >>= 1) {
        if (tid < o) {
            if (sv[tid + o] > sv[tid] ||
                (sv[tid + o] == sv[tid] && si[tid + o] < si[tid])) {
                sv[tid] = sv[tid + o]; si[tid] = si[tid + o];
            }
        }
        __syncthreads();
    }
    int off = si[0];
    for (int t = tid; t < Tt; t += 256) {
        int v = seg[b * Tt + t];
        g_pos[b * Tt + t] = (v != 0) ? (t - off) : (1 << 30);
    }
}

// ---------------------------------------------------------------------------
// fp32 -> (hi, lo) bf16 split, elementwise
// ---------------------------------------------------------------------------
__global__ __launch_bounds__(256)
void conv_split(const float* __restrict__ src, __nv_bfloat16* __restrict__ hi,
                __nv_bfloat16* __restrict__ lo, size_t n4) {
    size_t i = (size_t)blockIdx.x * blockDim.x + threadIdx.x;
    size_t stride = (size_t)gridDim.x * blockDim.x;
    for (; i < n4; i += stride) {
        float4 v = ((const float4*)src)[i];
        __nv_bfloat16 h0 = __float2bfloat16(v.x);
        __nv_bfloat16 h1 = __float2bfloat16(v.y);
        __nv_bfloat16 h2 = __float2bfloat16(v.z);
        __nv_bfloat16 h3 = __float2bfloat16(v.w);
        __nv_bfloat16 l0 = __float2bfloat16(v.x - __bfloat162float(h0));
        __nv_bfloat16 l1 = __float2bfloat16(v.y - __bfloat162float(h1));
        __nv_bfloat16 l2 = __float2bfloat16(v.z - __bfloat162float(h2));
        __nv_bfloat16 l3 = __float2bfloat16(v.w - __bfloat162float(h3));
        ((ushort4*)hi)[i] = make_ushort4(__bfloat16_as_ushort(h0), __bfloat16_as_ushort(h1),
                                         __bfloat16_as_ushort(h2), __bfloat16_as_ushort(h3));
        ((ushort4*)lo)[i] = make_ushort4(__bfloat16_as_ushort(l0), __bfloat16_as_ushort(l1),
                                         __bfloat16_as_ushort(l2), __bfloat16_as_ushort(l3));
    }
}

// ---------------------------------------------------------------------------
// Transpose + split: w[Kd, Nc] fp32 -> wT_hi/lo[Nc, Kd] bf16
// ---------------------------------------------------------------------------
__global__ __launch_bounds__(256)
void conv_tsplit(const float* __restrict__ w, __nv_bfloat16* __restrict__ hi,
                 __nv_bfloat16* __restrict__ lo, int Kd, int Nc) {
    __shared__ float t[32][33];
    int n0 = blockIdx.x * 32, k0 = blockIdx.y * 32;
    int tx = threadIdx.x, ty = threadIdx.y;
    for (int i = ty; i < 32; i += 8)
        t[i][tx] = w[(size_t)(k0 + i) * Nc + n0 + tx];
    __syncthreads();
    for (int i = ty; i < 32; i += 8) {
        float v = t[tx][i];
        __nv_bfloat16 h = __float2bfloat16(v);
        __nv_bfloat16 l = __float2bfloat16(v - __bfloat162float(h));
        size_t o = (size_t)(n0 + i) * Kd + k0 + tx;
        hi[o] = h; lo[o] = l;
    }
}

// ---------------------------------------------------------------------------
// HMMA (mma.sync) bf16-split GEMM: C[M,Nc] = A[M,Kd] x Bt[Nc,Kd]^T
// 128x128 tile, BK=64, 256 threads (8 warps, 4x2), cp.async double buffer.
// ---------------------------------------------------------------------------
#define GSTAGE 65536                       // 4 x 16KB (Ahi, Alo, Bhi, Blo)
#define GEMM_SMEM (2 * GSTAGE)

__global__ __launch_bounds__(256)
void gemm_hmma(const __nv_bfloat16* __restrict__ Ahi, const __nv_bfloat16* __restrict__ Alo,
               const __nv_bfloat16* __restrict__ Bhi, const __nv_bfloat16* __restrict__ Blo,
               float* __restrict__ C, int Nc, int Kd) {
    extern __shared__ char smc[];
    const int tid  = threadIdx.x;
    const int lane = tid & 31;
    const int wid  = tid >> 5;
    const int warp_m = wid & 3;            // 0..3 -> 32-row slab
    const int warp_n = wid >> 2;           // 0..1 -> 64-col slab
    const int m0 = blockIdx.y * 128, n0 = blockIdx.x * 128;

    const int u = tid & 7;                 // 16B unit in 128B row
    const int r = tid >> 3;                // 0..31

    const uint32_t sbase = smem_u32(smc);
    const int nchunk = Kd >> 6;

    float d[2][8][4];
#pragma unroll
    for (int mt = 0; mt < 2; mt++)
#pragma unroll
        for (int nt = 0; nt < 8; nt++)
#pragma unroll
            for (int j = 0; j < 4; j++) d[mt][nt][j] = 0.f;

    // stage loader: chunk c -> buffer s
#define ISSUE_CHUNK(c, s) do {                                               \
    const int k0e = (c) * 64;                                                \
    char* buf = smc + (s) * GSTAGE;                                          \
    _Pragma("unroll")                                                        \
    for (int i = 0; i < 4; i++) {                                            \
        int row = r + i * 32;                                                \
        uint32_t so = SW128(row * 128 + u * 16);                             \
        uint32_t sa = smem_u32(buf) + so;                                    \
        const __nv_bfloat16* pa_hi = Ahi + (size_t)(m0 + row) * Kd + k0e + u * 8; \
        const __nv_bfloat16* pa_lo = Alo + (size_t)(m0 + row) * Kd + k0e + u * 8; \
        const __nv_bfloat16* pb_hi = Bhi + (size_t)(n0 + row) * Kd + k0e + u * 8; \
        const __nv_bfloat16* pb_lo = Blo + (size_t)(n0 + row) * Kd + k0e + u * 8; \
        CP_ASYNC16(sa,         pa_hi);                                       \
        CP_ASYNC16(sa + 16384, pa_lo);                                       \
        CP_ASYNC16(sa + 32768, pb_hi);                                       \
        CP_ASYNC16(sa + 49152, pb_lo);                                       \
    }                                                                        \
} while (0)

    ISSUE_CHUNK(0, 0);
    CP_COMMIT();

    for (int c = 0; c < nchunk; c++) {
        if (c + 1 < nchunk) { ISSUE_CHUNK(c + 1, (c + 1) & 1); CP_COMMIT(); CP_WAIT(1); }
        else                { CP_WAIT(0); }
        __syncthreads();

        const uint32_t sb = sbase + (c & 1) * GSTAGE;
#pragma unroll
        for (int s = 0; s < 4; s++) {
            // A fragments (2 m-tiles, hi+lo)
            uint32_t aH[2][4], aL[2][4];
#pragma unroll
            for (int mt = 0; mt < 2; mt++) {
                int row  = warp_m * 32 + mt * 16 + (lane & 7) + ((lane >> 3) & 1) * 8;
                int unit = s * 2 + (lane >> 4);
                uint32_t addr = sb + SW128(row * 128 + unit * 16);
                LDSM_X4(aH[mt], addr);
                LDSM_X4(aL[mt], addr + 16384);
            }
            // B fragments (8 n-tiles as 4 pairs, hi+lo)
            uint32_t bH[8][2], bL[8][2];
#pragma unroll
            for (int np = 0; np < 4; np++) {
                int row  = warp_n * 64 + np * 16 + ((lane >> 4) & 1) * 8 + (lane & 7);
                int unit = s * 2 + ((lane >> 3) & 1);
                uint32_t addr = sb + 32768 + SW128(row * 128 + unit * 16);
                uint32_t tmp[4];
                LDSM_X4(tmp, addr);
                bH[2*np][0] = tmp[0]; bH[2*np][1] = tmp[1];
                bH[2*np+1][0] = tmp[2]; bH[2*np+1][1] = tmp[3];
                LDSM_X4(tmp, addr + 16384);
                bL[2*np][0] = tmp[0]; bL[2*np][1] = tmp[1];
                bL[2*np+1][0] = tmp[2]; bL[2*np+1][1] = tmp[3];
            }
#pragma unroll
            for (int mt = 0; mt < 2; mt++)
#pragma unroll
                for (int nt = 0; nt < 8; nt++) {
                    MMA16816(d[mt][nt], aH[mt], bH[nt]);
                    MMA16816(d[mt][nt], aH[mt], bL[nt]);
                    MMA16816(d[mt][nt], aL[mt], bH[nt]);
                }
        }
        __syncthreads();
    }

    // epilogue: direct global store (float2 per row-pair)
#pragma unroll
    for (int mt = 0; mt < 2; mt++) {
#pragma unroll
        for (int nt = 0; nt < 8; nt++) {
            int row = m0 + warp_m * 32 + mt * 16 + (lane >> 2);
            int col = n0 + warp_n * 64 + nt * 8 + (lane & 3) * 2;
            *(float2*)&C[(size_t)row * Nc + col] =
                make_float2(d[mt][nt][0], d[mt][nt][1]);
            *(float2*)&C[(size_t)(row + 8) * Nc + col] =
                make_float2(d[mt][nt][2], d[mt][nt][3]);
        }
    }
#undef ISSUE_CHUNK
}

// ---------------------------------------------------------------------------
// Fused RMSNorm + RoPE over rows of H=128.
// ---------------------------------------------------------------------------
__global__ __launch_bounds__(128)
void norm_rope_kernel(float* __restrict__ buf, const float* __restrict__ scale,
                      int heads) {
    const int row  = blockIdx.x;
    const int h    = threadIdx.x;
    const int trow = row / heads;

    float v = buf[(size_t)row * Hh + h];
    float ss = v * v;
#pragma unroll
    for (int o = 16; o; o >>= 1) ss += __shfl_xor_sync(0xffffffffu, ss, o);
    __shared__ float warpsum[4];
    __shared__ float s_n[Hh];
    if ((h & 31) == 0) warpsum[h >> 5] = ss;
    __syncthreads();
    float total = warpsum[0] + warpsum[1] + warpsum[2] + warpsum[3];
    float inv_rms = rsqrtf(total * (1.0f / 128.0f) + EPSf);
    s_n[h] = v * inv_rms * scale[h];
    __syncthreads();

    int pos = g_pos[trow];
    int i = h & 63;
    float inv_freq = __expf(-(float)i * (LOG_THETA / 64.0f));
    float ang = (float)pos * inv_freq;
    float sn = sinf(ang), cs = cosf(ang);
    float out = (h < 64) ? (s_n[h] * cs - s_n[h + 64] * sn)
                         : (s_n[h] * cs + s_n[h - 64] * sn);
    buf[(size_t)row * Hh + h] = out;
}

// ---------------------------------------------------------------------------
// Flash attention, fp32, 64x64 tiles, online softmax
// ---------------------------------------------------------------------------
#define QT 64
#define KT 64
#define QPAD 129
#define SPAD 65

__global__ __launch_bounds__(256)
void attn_kernel(const int* __restrict__ seg) {
    extern __shared__ char sm_raw[];
    float* sQ = (float*)sm_raw;
    float* sK = sQ + QT * QPAD;
    float* sV = sK + KT * QPAD;
    float* sS = sV + KT * QPAD;
    float* sM = sS + QT * SPAD;
    float* sL = sM + QT;
    float* sA = sL + QT;
    int* sQpos = (int*)(sA + QT);
    int* sQseg = sQpos + QT;
    int* sKpos = sQseg + QT;
    int* sKseg = sKpos + KT;
    int* sCtl  = sKseg + KT;

    const int tid   = threadIdx.x;
    const int qbase = blockIdx.x * QT;
    const int n     = blockIdx.y;
    const int b     = blockIdx.z;
    const int kvh   = n / Gg;

    for (int idx = tid; idx < QT * Hh; idx += 256) {
        int qi = idx >> 7, h = idx & 127;
        sQ[qi * QPAD + h] =
            g_q[(((size_t)(b * Tt + qbase + qi)) * Nn + n) * Hh + h] * SCALEf;
    }
    if (tid < QT) {
        sQpos[tid] = g_pos[b * Tt + qbase + tid];
        sQseg[tid] = seg[b * Tt + qbase + tid];
        sM[tid] = -1e30f;
        sL[tid] = 0.f;
    }
    __syncthreads();
    if (tid == 0) {
        int mx = INT_MIN;
        for (int j = 0; j < QT; j++) mx = max(mx, sQpos[j]);
        sCtl[0] = mx;
    }
    __syncthreads();
    const int qmax = sCtl[0];

    const int ty = tid >> 4, tx = tid & 15;
    const int oq = tid >> 2, od = tid & 3;
    float acc[32];
#pragma unroll
    for (int j = 0; j < 32; j++) acc[j] = 0.f;

    for (int kt = 0; kt < Tt / KT; ++kt) {
        const int sbase = kt * KT;
        if (tid < KT) {
            sKpos[tid] = g_pos[b * Tt + sbase + tid];
            sKseg[tid] = seg[b * Tt + sbase + tid];
        }
        __syncthreads();
        if (tid == 0) {
            int kmin = INT_MAX;
            for (int j = 0; j < KT; j++) kmin = min(kmin, sKpos[j]);
            sCtl[1] = (kmin > qmax) ? 1 : 0;
        }
        __syncthreads();
        if (sCtl[1]) { __syncthreads(); continue; }

        for (int idx = tid; idx < KT * Hh; idx += 256) {
            int s = idx >> 7, h = idx & 127;
            size_t basei = (((size_t)(b * Tt + sbase + s)) * Kk + kvh) * Hh + h;
            sK[s * QPAD + h] = g_k[basei];
            sV[s * QPAD + h] = g_v[basei];
        }
        __syncthreads();

        float as[4][4];
#pragma unroll
        for (int rr = 0; rr < 4; rr++)
#pragma unroll
            for (int cc = 0; cc < 4; cc++) as[rr][cc] = 0.f;
        for (int k = 0; k < Hh; k++) {
            float a[4], bv[4];
#pragma unroll
            for (int rr = 0; rr < 4; rr++) a[rr] = sQ[(ty * 4 + rr) * QPAD + k];
#pragma unroll
            for (int cc = 0; cc < 4; cc++) bv[cc] = sK[(tx * 4 + cc) * QPAD + k];
#pragma unroll
            for (int rr = 0; rr < 4; rr++)
#pragma unroll
                for (int cc = 0; cc < 4; cc++) as[rr][cc] += a[rr] * bv[cc];
        }
#pragma unroll
        for (int rr = 0; rr < 4; rr++) {
#pragma unroll
            for (int cc = 0; cc < 4; cc++) {
                int i = ty * 4 + rr, j = tx * 4 + cc;
                bool ok = (sKpos[j] <= sQpos[i]) && (sKseg[j] == sQseg[i]);
                sS[i * SPAD + j] = ok ? as[rr][cc] : -1e30f;
            }
        }
        __syncthreads();

        if (tid < QT) {
            int i = tid;
            float m_old = sM[i];
            float mx = -1e30f;
#pragma unroll 8
            for (int j = 0; j < KT; j++) mx = fmaxf(mx, sS[i * SPAD + j]);
            float new_m = fmaxf(m_old, mx);
            bool dead = (new_m < -0.9e30f);
            float alpha = dead ? 1.f : __expf(m_old - new_m);
            float lsum = 0.f;
#pragma unroll 8
            for (int j = 0; j < KT; j++) {
                float p = dead ? 0.f : __expf(sS[i * SPAD + j] - new_m);
                sS[i * SPAD + j] = p;
                lsum += p;
            }
            sL[i] = sL[i] * alpha + lsum;
            sM[i] = new_m;
            sA[i] = alpha;
        }
        __syncthreads();

        float alpha = sA[oq];
#pragma unroll
        for (int j = 0; j < 32; j++) acc[j] *= alpha;
        for (int s = 0; s < KT; s++) {
            float p = sS[oq * SPAD + s];
            const float* vr = &sV[s * QPAD + od];
#pragma unroll
            for (int j = 0; j < 32; j++) acc[j] += p * vr[4 * j];
        }
        __syncthreads();
    }

    float l = sL[oq];
    float inv_l = (l > 0.f) ? (1.f / l) : 0.f;
    size_t obase = (((size_t)(b * Tt + qbase + oq)) * Nn + n) * Hh + od;
#pragma unroll
    for (int j = 0; j < 32; j++) g_att[obase + 4 * j] = acc[j] * inv_l;
}

// ---------------------------------------------------------------------------
extern "C" void kernel_launch(void* const* d_in, const int* in_sizes, int n_in,
                              void* d_out, int out_size) {
    const float* x       = (const float*)d_in[0];
    const int*   seg     = (const int*)  d_in[1];
    const float* wq      = (const float*)d_in[2];
    const float* wk      = (const float*)d_in[3];
    const float* wv      = (const float*)d_in[4];
    const float* wo      = (const float*)d_in[5];
    const float* q_scale = (const float*)d_in[6];
    const float* k_scale = (const float*)d_in[7];
    float* out = (float*)d_out;

    float *qp, *kp, *vp, *ap;
    cudaGetSymbolAddress((void**)&qp, g_q);
    cudaGetSymbolAddress((void**)&kp, g_k);
    cudaGetSymbolAddress((void**)&vp, g_v);
    cudaGetSymbolAddress((void**)&ap, g_att);
    __nv_bfloat16 *xhi, *xlo, *ahi, *alo;
    __nv_bfloat16 *wqh, *wql, *wkh, *wkl, *wvh, *wvl, *woh, *wol;
    cudaGetSymbolAddress((void**)&xhi, g_xhi);
    cudaGetSymbolAddress((void**)&xlo, g_xlo);
    cudaGetSymbolAddress((void**)&ahi, g_atthi);
    cudaGetSymbolAddress((void**)&alo, g_attlo);
    cudaGetSymbolAddress((void**)&wqh, g_wqT_hi);
    cudaGetSymbolAddress((void**)&wql, g_wqT_lo);
    cudaGetSymbolAddress((void**)&wkh, g_wkT_hi);
    cudaGetSymbolAddress((void**)&wkl, g_wkT_lo);
    cudaGetSymbolAddress((void**)&wvh, g_wvT_hi);
    cudaGetSymbolAddress((void**)&wvl, g_wvT_lo);
    cudaGetSymbolAddress((void**)&woh, g_woT_hi);
    cudaGetSymbolAddress((void**)&wol, g_woT_lo);

    cudaFuncSetAttribute(gemm_hmma, cudaFuncAttributeMaxDynamicSharedMemorySize,
                         GEMM_SMEM);
    size_t smem_attn =
        (size_t)(3 * QT * QPAD + QT * SPAD + 3 * QT) * sizeof(float) +
        (size_t)(4 * QT + 8) * sizeof(int);
    cudaFuncSetAttribute(attn_kernel, cudaFuncAttributeMaxDynamicSharedMemorySize,
                         (int)smem_attn);

    pos_kernel<<<Bb, 256>>>(seg);

    // split conversions
    conv_split<<<1024, 256>>>(x, xhi, xlo, (size_t)Mrows * Dd / 4);
    conv_tsplit<<<dim3(2048 / 32, 1024 / 32), dim3(32, 8)>>>(wq, wqh, wql, 1024, 2048);
    conv_tsplit<<<dim3(1024 / 32, 1024 / 32), dim3(32, 8)>>>(wk, wkh, wkl, 1024, 1024);
    conv_tsplit<<<dim3(1024 / 32, 1024 / 32), dim3(32, 8)>>>(wv, wvh, wvl, 1024, 1024);
    conv_tsplit<<<dim3(1024 / 32, 2048 / 32), dim3(32, 8)>>>(wo, woh, wol, 2048, 1024);

    // QKV projections on HMMA tensor cores
    gemm_hmma<<<dim3(2048 / 128, Mrows / 128), 256, GEMM_SMEM>>>(xhi, xlo, wqh, wql, qp, 2048, 1024);
    gemm_hmma<<<dim3(1024 / 128, Mrows / 128), 256, GEMM_SMEM>>>(xhi, xlo, wkh, wkl, kp, 1024, 1024);
    gemm_hmma<<<dim3(1024 / 128, Mrows / 128), 256, GEMM_SMEM>>>(xhi, xlo, wvh, wvl, vp, 1024, 1024);

    norm_rope_kernel<<<Mrows * Nn, 128>>>(qp, q_scale, Nn);
    norm_rope_kernel<<<Mrows * Kk, 128>>>(kp, k_scale, Kk);

    attn_kernel<<<dim3(Tt / QT, Nn, Bb), 256, smem_attn>>>(seg);

    // output projection
    conv_split<<<1024, 256>>>(ap, ahi, alo, (size_t)Mrows * Nn * Hh / 4);
    gemm_hmma<<<dim3(1024 / 128, Mrows / 128), 256, GEMM_SMEM>>>(ahi, alo, woh, wol, out, 1024, 2048);
}

// round 6
// speedup vs baseline: 3.8917x; 3.0217x over previous
#include <cuda_runtime.h>
#include <cuda_bf16.h>
#include <math.h>
#include <float.h>
#include <limits.h>
#include <stdint.h>

// Problem constants
#define Bb 2
#define Tt 2048
#define Dd 1024
#define Nn 16
#define Kk 8
#define Hh 128
#define Gg 2
#define Mrows (Bb*Tt)          // 4096

static constexpr float EPSf   = 1e-6f;
static constexpr float LOG_THETA = 13.815510557964274f;  // ln(1e6)
static constexpr float SCALEf = 0.08838834764831845f;    // 128^-0.5

// ---------------------------------------------------------------------------
// Scratch (allocation-free rule: __device__ globals)
// ---------------------------------------------------------------------------
__device__ float g_q[(size_t)Mrows * Nn * Hh];   // fp32 gemm out (pre-norm)
__device__ float g_k[(size_t)Mrows * Kk * Hh];
__device__ float g_v[(size_t)Mrows * Kk * Hh];
__device__ int   g_pos[Mrows];

// bf16 split buffers
__device__ __nv_bfloat16 g_xhi[(size_t)Mrows * Dd];
__device__ __nv_bfloat16 g_xlo[(size_t)Mrows * Dd];
__device__ __nv_bfloat16 g_atthi[(size_t)Mrows * Nn * Hh];   // attn out (row-major [row][n*H])
__device__ __nv_bfloat16 g_attlo[(size_t)Mrows * Nn * Hh];
__device__ __nv_bfloat16 g_wqT_hi[(size_t)(Nn*Hh) * Dd];
__device__ __nv_bfloat16 g_wqT_lo[(size_t)(Nn*Hh) * Dd];
__device__ __nv_bfloat16 g_wkT_hi[(size_t)(Kk*Hh) * Dd];
__device__ __nv_bfloat16 g_wkT_lo[(size_t)(Kk*Hh) * Dd];
__device__ __nv_bfloat16 g_wvT_hi[(size_t)(Kk*Hh) * Dd];
__device__ __nv_bfloat16 g_wvT_lo[(size_t)(Kk*Hh) * Dd];
__device__ __nv_bfloat16 g_woT_hi[(size_t)Dd * (Nn*Hh)];
__device__ __nv_bfloat16 g_woT_lo[(size_t)Dd * (Nn*Hh)];

// head-major bf16 split q/k/v for attention: [b][head][t][h]
__device__ __nv_bfloat16 g_qhh[(size_t)Bb * Nn * Tt * Hh];
__device__ __nv_bfloat16 g_qhl[(size_t)Bb * Nn * Tt * Hh];
__device__ __nv_bfloat16 g_khh[(size_t)Bb * Kk * Tt * Hh];
__device__ __nv_bfloat16 g_khl[(size_t)Bb * Kk * Tt * Hh];
__device__ __nv_bfloat16 g_vhh[(size_t)Bb * Kk * Tt * Hh];
__device__ __nv_bfloat16 g_vhl[(size_t)Bb * Kk * Tt * Hh];

// ---------------------------------------------------------------------------
// PTX helpers (sm_103 baseline ISA: cp.async, ldmatrix, mma.sync)
// ---------------------------------------------------------------------------
__device__ __forceinline__ uint32_t smem_u32(const void* p) {
    uint32_t a;
    asm("{ .reg .u64 t; cvta.to.shared.u64 t, %1; cvt.u32.u64 %0, t; }"
        : "=r"(a) : "l"(p));
    return a;
}
#define SW128(off) ((off) ^ (((off) >> 3) & 0x70))

#define CP_ASYNC16(saddr, gaddr) \
    asm volatile("cp.async.cg.shared.global [%0], [%1], 16;" \
        :: "r"(saddr), "l"(gaddr) : "memory")
#define CP_COMMIT() asm volatile("cp.async.commit_group;" ::: "memory")
#define CP_WAIT(n)  asm volatile("cp.async.wait_group %0;" :: "n"(n) : "memory")

#define LDSM_X4(r, addr) \
    asm volatile("ldmatrix.sync.aligned.m8n8.x4.shared.b16 {%0,%1,%2,%3}, [%4];" \
        : "=r"((r)[0]), "=r"((r)[1]), "=r"((r)[2]), "=r"((r)[3]) : "r"(addr))
#define LDSM_X4_T(r, addr) \
    asm volatile("ldmatrix.sync.aligned.m8n8.x4.trans.shared.b16 {%0,%1,%2,%3}, [%4];" \
        : "=r"((r)[0]), "=r"((r)[1]), "=r"((r)[2]), "=r"((r)[3]) : "r"(addr))

#define MMA16816(d, a, b0r, b1r) \
    asm volatile("mma.sync.aligned.m16n8k16.row.col.f32.bf16.bf16.f32 " \
        "{%0,%1,%2,%3}, {%4,%5,%6,%7}, {%8,%9}, {%0,%1,%2,%3};" \
        : "+f"((d)[0]), "+f"((d)[1]), "+f"((d)[2]), "+f"((d)[3]) \
        : "r"((a)[0]), "r"((a)[1]), "r"((a)[2]), "r"((a)[3]), \
          "r"((b0r)), "r"((b1r)))

// Split fp32 pair into packed bf16 hi + packed bf16 residual.
__device__ __forceinline__ uint32_t split2(float x0, float x1, uint32_t& lopack) {
    __nv_bfloat16 h0 = __float2bfloat16(x0), h1 = __float2bfloat16(x1);
    float r0 = x0 - __bfloat162float(h0), r1 = x1 - __bfloat162float(h1);
    __nv_bfloat16 g0 = __float2bfloat16(r0), g1 = __float2bfloat16(r1);
    lopack = (uint32_t)__bfloat16_as_ushort(g0) | ((uint32_t)__bfloat16_as_ushort(g1) << 16);
    return (uint32_t)__bfloat16_as_ushort(h0) | ((uint32_t)__bfloat16_as_ushort(h1) << 16);
}

// ---------------------------------------------------------------------------
// positions_from_segment_ids
// ---------------------------------------------------------------------------
__global__ void pos_kernel(const int* __restrict__ seg) {
    int b = blockIdx.x;
    int tid = threadIdx.x;
    __shared__ int sv[256], si[256];
    int bv = INT_MIN, bi = INT_MAX;
    for (int t = tid; t < Tt; t += 256) {
        int v = seg[b * Tt + t];
        if (v > bv) { bv = v; bi = t; }
    }
    sv[tid] = bv; si[tid] = bi;
    __syncthreads();
    for (int o = 128; o; o >>= 1) {
        if (tid < o) {
            if (sv[tid + o] > sv[tid] ||
                (sv[tid + o] == sv[tid] && si[tid + o] < si[tid])) {
                sv[tid] = sv[tid + o]; si[tid] = si[tid + o];
            }
        }
        __syncthreads();
    }
    int off = si[0];
    for (int t = tid; t < Tt; t += 256) {
        int v = seg[b * Tt + t];
        g_pos[b * Tt + t] = (v != 0) ? (t - off) : (1 << 30);
    }
}

// ---------------------------------------------------------------------------
// fp32 -> (hi, lo) bf16 split, elementwise
// ---------------------------------------------------------------------------
__global__ __launch_bounds__(256)
void conv_split(const float* __restrict__ src, __nv_bfloat16* __restrict__ hi,
                __nv_bfloat16* __restrict__ lo, size_t n4) {
    size_t i = (size_t)blockIdx.x * blockDim.x + threadIdx.x;
    size_t stride = (size_t)gridDim.x * blockDim.x;
    for (; i < n4; i += stride) {
        float4 v = ((const float4*)src)[i];
        uint32_t l01, l23;
        uint32_t h01 = split2(v.x, v.y, l01);
        uint32_t h23 = split2(v.z, v.w, l23);
        ((uint2*)hi)[i] = make_uint2(h01, h23);
        ((uint2*)lo)[i] = make_uint2(l01, l23);
    }
}

// ---------------------------------------------------------------------------
// Transpose + split: w[Kd, Nc] fp32 -> wT_hi/lo[Nc, Kd] bf16
// ---------------------------------------------------------------------------
__global__ __launch_bounds__(256)
void conv_tsplit(const float* __restrict__ w, __nv_bfloat16* __restrict__ hi,
                 __nv_bfloat16* __restrict__ lo, int Kd, int Nc) {
    __shared__ float t[32][33];
    int n0 = blockIdx.x * 32, k0 = blockIdx.y * 32;
    int tx = threadIdx.x, ty = threadIdx.y;
    for (int i = ty; i < 32; i += 8)
        t[i][tx] = w[(size_t)(k0 + i) * Nc + n0 + tx];
    __syncthreads();
    for (int i = ty; i < 32; i += 8) {
        float v = t[tx][i];
        __nv_bfloat16 h = __float2bfloat16(v);
        __nv_bfloat16 l = __float2bfloat16(v - __bfloat162float(h));
        size_t o = (size_t)(n0 + i) * Kd + k0 + tx;
        hi[o] = h; lo[o] = l;
    }
}

// ---------------------------------------------------------------------------
// HMMA (mma.sync) bf16-split GEMM: C[M,Nc] = A[M,Kd] x Bt[Nc,Kd]^T
// ---------------------------------------------------------------------------
#define GSTAGE 65536
#define GEMM_SMEM (2 * GSTAGE)

__global__ __launch_bounds__(256)
void gemm_hmma(const __nv_bfloat16* __restrict__ Ahi, const __nv_bfloat16* __restrict__ Alo,
               const __nv_bfloat16* __restrict__ Bhi, const __nv_bfloat16* __restrict__ Blo,
               float* __restrict__ C, int Nc, int Kd) {
    extern __shared__ char smc[];
    const int tid  = threadIdx.x;
    const int lane = tid & 31;
    const int wid  = tid >> 5;
    const int warp_m = wid & 3;
    const int warp_n = wid >> 2;
    const int m0 = blockIdx.y * 128, n0 = blockIdx.x * 128;

    const int u = tid & 7;
    const int r = tid >> 3;

    const uint32_t sbase = smem_u32(smc);
    const int nchunk = Kd >> 6;

    float d[2][8][4];
#pragma unroll
    for (int mt = 0; mt < 2; mt++)
#pragma unroll
        for (int nt = 0; nt < 8; nt++)
#pragma unroll
            for (int j = 0; j < 4; j++) d[mt][nt][j] = 0.f;

#define ISSUE_CHUNK(c, s) do {                                               \
    const int k0e = (c) * 64;                                                \
    char* buf = smc + (s) * GSTAGE;                                          \
    _Pragma("unroll")                                                        \
    for (int i = 0; i < 4; i++) {                                            \
        int row = r + i * 32;                                                \
        uint32_t so = SW128(row * 128 + u * 16);                             \
        uint32_t sa = smem_u32(buf) + so;                                    \
        const __nv_bfloat16* pa_hi = Ahi + (size_t)(m0 + row) * Kd + k0e + u * 8; \
        const __nv_bfloat16* pa_lo = Alo + (size_t)(m0 + row) * Kd + k0e + u * 8; \
        const __nv_bfloat16* pb_hi = Bhi + (size_t)(n0 + row) * Kd + k0e + u * 8; \
        const __nv_bfloat16* pb_lo = Blo + (size_t)(n0 + row) * Kd + k0e + u * 8; \
        CP_ASYNC16(sa,         pa_hi);                                       \
        CP_ASYNC16(sa + 16384, pa_lo);                                       \
        CP_ASYNC16(sa + 32768, pb_hi);                                       \
        CP_ASYNC16(sa + 49152, pb_lo);                                       \
    }                                                                        \
} while (0)

    ISSUE_CHUNK(0, 0);
    CP_COMMIT();

    for (int c = 0; c < nchunk; c++) {
        if (c + 1 < nchunk) { ISSUE_CHUNK(c + 1, (c + 1) & 1); CP_COMMIT(); CP_WAIT(1); }
        else                { CP_WAIT(0); }
        __syncthreads();

        const uint32_t sb = sbase + (c & 1) * GSTAGE;
#pragma unroll
        for (int s = 0; s < 4; s++) {
            uint32_t aH[2][4], aL[2][4];
#pragma unroll
            for (int mt = 0; mt < 2; mt++) {
                int row  = warp_m * 32 + mt * 16 + (lane & 7) + ((lane >> 3) & 1) * 8;
                int unit = s * 2 + (lane >> 4);
                uint32_t addr = sb + SW128(row * 128 + unit * 16);
                LDSM_X4(aH[mt], addr);
                LDSM_X4(aL[mt], addr + 16384);
            }
            uint32_t bH[8][2], bL[8][2];
#pragma unroll
            for (int np = 0; np < 4; np++) {
                int row  = warp_n * 64 + np * 16 + ((lane >> 4) & 1) * 8 + (lane & 7);
                int unit = s * 2 + ((lane >> 3) & 1);
                uint32_t addr = sb + 32768 + SW128(row * 128 + unit * 16);
                uint32_t tmp[4];
                LDSM_X4(tmp, addr);
                bH[2*np][0] = tmp[0]; bH[2*np][1] = tmp[1];
                bH[2*np+1][0] = tmp[2]; bH[2*np+1][1] = tmp[3];
                LDSM_X4(tmp, addr + 16384);
                bL[2*np][0] = tmp[0]; bL[2*np][1] = tmp[1];
                bL[2*np+1][0] = tmp[2]; bL[2*np+1][1] = tmp[3];
            }
#pragma unroll
            for (int mt = 0; mt < 2; mt++)
#pragma unroll
                for (int nt = 0; nt < 8; nt++) {
                    MMA16816(d[mt][nt], aH[mt], bH[nt][0], bH[nt][1]);
                    MMA16816(d[mt][nt], aH[mt], bL[nt][0], bL[nt][1]);
                    MMA16816(d[mt][nt], aL[mt], bH[nt][0], bH[nt][1]);
                }
        }
        __syncthreads();
    }

#pragma unroll
    for (int mt = 0; mt < 2; mt++) {
#pragma unroll
        for (int nt = 0; nt < 8; nt++) {
            int row = m0 + warp_m * 32 + mt * 16 + (lane >> 2);
            int col = n0 + warp_n * 64 + nt * 8 + (lane & 3) * 2;
            *(float2*)&C[(size_t)row * Nc + col] =
                make_float2(d[mt][nt][0], d[mt][nt][1]);
            *(float2*)&C[(size_t)(row + 8) * Nc + col] =
                make_float2(d[mt][nt][2], d[mt][nt][3]);
        }
    }
#undef ISSUE_CHUNK
}

// ---------------------------------------------------------------------------
// Fused RMSNorm + RoPE + bf16 split + head-major store.
// in layout: [(b*T+t)*heads + n][H]; out: [b][n][t][H] hi/lo bf16.
// ---------------------------------------------------------------------------
__global__ __launch_bounds__(128)
void norm_rope_split(const float* __restrict__ in, const float* __restrict__ scale,
                     __nv_bfloat16* __restrict__ outhi, __nv_bfloat16* __restrict__ outlo,
                     int heads, float post_scale) {
    const int row  = blockIdx.x;
    const int h    = threadIdx.x;
    const int trow = row / heads;
    const int n    = row - trow * heads;
    const int b    = trow >> 11;          // Tt = 2048
    const int t    = trow & 2047;

    float v = in[(size_t)row * Hh + h];
    float ss = v * v;
#pragma unroll
    for (int o = 16; o; o >>= 1) ss += __shfl_xor_sync(0xffffffffu, ss, o);
    __shared__ float warpsum[4];
    __shared__ float s_n[Hh];
    if ((h & 31) == 0) warpsum[h >> 5] = ss;
    __syncthreads();
    float total = warpsum[0] + warpsum[1] + warpsum[2] + warpsum[3];
    float inv_rms = rsqrtf(total * (1.0f / 128.0f) + EPSf);
    s_n[h] = v * inv_rms * scale[h];
    __syncthreads();

    int pos = g_pos[trow];
    int i = h & 63;
    float inv_freq = __expf(-(float)i * (LOG_THETA / 64.0f));
    float ang = (float)pos * inv_freq;
    float sn = sinf(ang), cs = cosf(ang);
    float out = (h < 64) ? (s_n[h] * cs - s_n[h + 64] * sn)
                         : (s_n[h] * cs + s_n[h - 64] * sn);
    out *= post_scale;
    __nv_bfloat16 hi = __float2bfloat16(out);
    __nv_bfloat16 lo = __float2bfloat16(out - __bfloat162float(hi));
    size_t o = ((size_t)(b * heads + n) * Tt + t) * Hh + h;
    outhi[o] = hi;
    outlo[o] = lo;
}

// ---------------------------------------------------------------------------
// V: fp32 row-major -> head-major bf16 hi/lo
// ---------------------------------------------------------------------------
__global__ __launch_bounds__(128)
void v_split(const float* __restrict__ v) {
    const int row = blockIdx.x;            // Mrows * Kk
    const int h   = threadIdx.x;
    const int trow = row >> 3;             // Kk = 8
    const int kv   = row & 7;
    const int b = trow >> 11, t = trow & 2047;
    float x = v[(size_t)row * Hh + h];
    __nv_bfloat16 hi = __float2bfloat16(x);
    __nv_bfloat16 lo = __float2bfloat16(x - __bfloat162float(hi));
    size_t o = ((size_t)(b * Kk + kv) * Tt + t) * Hh + h;
    g_vhh[o] = hi;
    g_vhl[o] = lo;
}

// ---------------------------------------------------------------------------
// HMMA flash attention. 64 q rows/block, 4 warps x 16 rows.
// Q/K/V split-bf16 in SW128 smem; S and O in registers; online softmax.
// Output: bf16 hi/lo split into g_atthi/g_attlo, layout [b*T+t][n*128+h].
// ---------------------------------------------------------------------------
#define ATT_SMEM (98304 + 1024)

__global__ __launch_bounds__(128)
void attn_hmma(const int* __restrict__ seg) {
    extern __shared__ char sm[];
    const uint32_t sb = smem_u32(sm);
    int* sKpos  = (int*)(sm + 98304);
    int* sKseg  = sKpos + 64;
    int* sQposA = sKseg + 64;
    int* sCtl   = sQposA + 64;

    const int tid = threadIdx.x, lane = tid & 31, warp = tid >> 5;
    const int qbase = blockIdx.x * 64;
    const int n = blockIdx.y, b = blockIdx.z;
    const int kvh = n >> 1;               // Gg = 2

    // ---- load Q tile (hi/lo) into smem panels ----
    const char* qh = (const char*)(g_qhh + ((size_t)(b * Nn + n) * Tt + qbase) * Hh);
    const char* ql = (const char*)(g_qhl + ((size_t)(b * Nn + n) * Tt + qbase) * Hh);
    for (int i = tid; i < 1024; i += 128) {
        int r = i >> 4, u = i & 15;
        uint32_t off = ((u >> 3) << 13) + SW128(r * 128 + (u & 7) * 16);
        *(uint4*)(sm + off)         = *(const uint4*)(qh + r * 256 + u * 16);
        *(uint4*)(sm + 16384 + off) = *(const uint4*)(ql + r * 256 + u * 16);
    }
    if (tid < 64) sQposA[tid] = g_pos[b * Tt + qbase + tid];
    __syncthreads();
    if (tid == 0) {
        int mx = INT_MIN;
        for (int j = 0; j < 64; j++) mx = max(mx, sQposA[j]);
        sCtl[0] = mx;
    }
    // per-lane q row info (rows r_lo, r_lo+8)
    const int r_lo = warp * 16 + (lane >> 2);
    const int qp0 = g_pos[b * Tt + qbase + r_lo];
    const int qp1 = g_pos[b * Tt + qbase + r_lo + 8];
    const int qs0 = seg[b * Tt + qbase + r_lo];
    const int qs1 = seg[b * Tt + qbase + r_lo + 8];
    __syncthreads();
    const int qmax = sCtl[0];

    const char* kh = (const char*)(g_khh + ((size_t)(b * Kk + kvh) * Tt) * Hh);
    const char* kl = (const char*)(g_khl + ((size_t)(b * Kk + kvh) * Tt) * Hh);
    const char* vh = (const char*)(g_vhh + ((size_t)(b * Kk + kvh) * Tt) * Hh);
    const char* vl = (const char*)(g_vhl + ((size_t)(b * Kk + kvh) * Tt) * Hh);

    float d_o[16][4];
#pragma unroll
    for (int nt = 0; nt < 16; nt++)
#pragma unroll
        for (int j = 0; j < 4; j++) d_o[nt][j] = 0.f;
    float m0 = -1e30f, m1 = -1e30f, l0 = 0.f, l1 = 0.f;

    // per-lane fragment address components
    const int qrow_l = warp * 16 + (lane & 7) + ((lane >> 3) & 1) * 8;   // Q A-frag row
    const int krow_l = ((lane >> 4) & 1) * 8 + (lane & 7);               // K B-frag row-in-16
    const int vrow_l = (((lane >> 3) & 1) << 3) + (lane & 7);            // V frag row-in-16
    const int qh_sel = (lane >> 4) << 3;                                 // +0/+8 h
    const int kh_sel = ((lane >> 3) & 1) << 3;
    const int vh_sel = (lane >> 4) << 3;

    for (int kt = 0; kt < Tt / 64; kt++) {
        const int sbase = kt * 64;
        if (tid < 64) {
            sKpos[tid] = g_pos[b * Tt + sbase + tid];
            sKseg[tid] = seg[b * Tt + sbase + tid];
        }
        __syncthreads();
        if (tid == 0) {
            int kmin = INT_MAX;
            for (int j = 0; j < 64; j++) kmin = min(kmin, sKpos[j]);
            sCtl[1] = (kmin > qmax) ? 1 : 0;
        }
        __syncthreads();
        if (sCtl[1]) continue;

        // ---- load K/V tiles (hi/lo) ----
        for (int i = tid; i < 1024; i += 128) {
            int r = i >> 4, u = i & 15;
            uint32_t off = ((u >> 3) << 13) + SW128(r * 128 + (u & 7) * 16);
            size_t go = (size_t)(sbase + r) * 256 + u * 16;
            *(uint4*)(sm + 32768 + off) = *(const uint4*)(kh + go);
            *(uint4*)(sm + 49152 + off) = *(const uint4*)(kl + go);
            *(uint4*)(sm + 65536 + off) = *(const uint4*)(vh + go);
            *(uint4*)(sm + 81920 + off) = *(const uint4*)(vl + go);
        }
        __syncthreads();

        // ---- S = Q K^T (16 x 64 per warp) ----
        float ds[8][4];
#pragma unroll
        for (int nt = 0; nt < 8; nt++)
#pragma unroll
            for (int j = 0; j < 4; j++) ds[nt][j] = 0.f;

#pragma unroll
        for (int ks = 0; ks < 8; ks++) {
            int hq = ks * 16 + qh_sel;
            uint32_t qoff = ((hq >> 6) << 13) + SW128(qrow_l * 128 + ((hq & 63) << 1));
            uint32_t aH[4], aL[4];
            LDSM_X4(aH, sb + qoff);
            LDSM_X4(aL, sb + 16384 + qoff);
            int hk = ks * 16 + kh_sel;
            uint32_t kpan = ((hk >> 6) << 13);
            uint32_t kcol = (hk & 63) << 1;
#pragma unroll
            for (int np = 0; np < 4; np++) {
                uint32_t addr = sb + 32768 + kpan +
                                SW128((np * 16 + krow_l) * 128 + kcol);
                uint32_t tH[4], tL[4];
                LDSM_X4(tH, addr);
                LDSM_X4(tL, addr + 16384);
                MMA16816(ds[2*np],   aH, tH[0], tH[1]);
                MMA16816(ds[2*np],   aH, tL[0], tL[1]);
                MMA16816(ds[2*np],   aL, tH[0], tH[1]);
                MMA16816(ds[2*np+1], aH, tH[2], tH[3]);
                MMA16816(ds[2*np+1], aH, tL[2], tL[3]);
                MMA16816(ds[2*np+1], aL, tH[2], tH[3]);
            }
        }

        // ---- mask ----
#pragma unroll
        for (int nt = 0; nt < 8; nt++) {
            int c = nt * 8 + (lane & 3) * 2;
            int kp0 = sKpos[c], kp1 = sKpos[c + 1];
            int ks0 = sKseg[c], ks1 = sKseg[c + 1];
            if (!(kp0 <= qp0 && ks0 == qs0)) ds[nt][0] = -1e30f;
            if (!(kp1 <= qp0 && ks1 == qs0)) ds[nt][1] = -1e30f;
            if (!(kp0 <= qp1 && ks0 == qs1)) ds[nt][2] = -1e30f;
            if (!(kp1 <= qp1 && ks1 == qs1)) ds[nt][3] = -1e30f;
        }

        // ---- online softmax (rows r_lo, r_lo+8) ----
        float tm0 = -1e30f, tm1 = -1e30f;
#pragma unroll
        for (int nt = 0; nt < 8; nt++) {
            tm0 = fmaxf(tm0, fmaxf(ds[nt][0], ds[nt][1]));
            tm1 = fmaxf(tm1, fmaxf(ds[nt][2], ds[nt][3]));
        }
        tm0 = fmaxf(tm0, __shfl_xor_sync(0xffffffffu, tm0, 1));
        tm0 = fmaxf(tm0, __shfl_xor_sync(0xffffffffu, tm0, 2));
        tm1 = fmaxf(tm1, __shfl_xor_sync(0xffffffffu, tm1, 1));
        tm1 = fmaxf(tm1, __shfl_xor_sync(0xffffffffu, tm1, 2));
        float nm0 = fmaxf(m0, tm0), nm1 = fmaxf(m1, tm1);
        float a0 = __expf(m0 - nm0), a1 = __expf(m1 - nm1);
        float gg0 = (nm0 > -0.9e30f) ? 1.f : 0.f;
        float gg1 = (nm1 > -0.9e30f) ? 1.f : 0.f;
        float s0 = 0.f, s1 = 0.f;
#pragma unroll
        for (int nt = 0; nt < 8; nt++) {
            ds[nt][0] = gg0 * __expf(ds[nt][0] - nm0);
            ds[nt][1] = gg0 * __expf(ds[nt][1] - nm0);
            ds[nt][2] = gg1 * __expf(ds[nt][2] - nm1);
            ds[nt][3] = gg1 * __expf(ds[nt][3] - nm1);
            s0 += ds[nt][0] + ds[nt][1];
            s1 += ds[nt][2] + ds[nt][3];
        }
        s0 += __shfl_xor_sync(0xffffffffu, s0, 1);
        s0 += __shfl_xor_sync(0xffffffffu, s0, 2);
        s1 += __shfl_xor_sync(0xffffffffu, s1, 1);
        s1 += __shfl_xor_sync(0xffffffffu, s1, 2);
        l0 = l0 * a0 + s0; m0 = nm0;
        l1 = l1 * a1 + s1; m1 = nm1;
#pragma unroll
        for (int nt = 0; nt < 16; nt++) {
            d_o[nt][0] *= a0; d_o[nt][1] *= a0;
            d_o[nt][2] *= a1; d_o[nt][3] *= a1;
        }

        // ---- pack P into hi/lo A-fragments ----
        uint32_t Ph[4][4], Pl[4][4];
#pragma unroll
        for (int kb = 0; kb < 4; kb++) {
            Ph[kb][0] = split2(ds[2*kb][0],   ds[2*kb][1],   Pl[kb][0]);
            Ph[kb][1] = split2(ds[2*kb][2],   ds[2*kb][3],   Pl[kb][1]);
            Ph[kb][2] = split2(ds[2*kb+1][0], ds[2*kb+1][1], Pl[kb][2]);
            Ph[kb][3] = split2(ds[2*kb+1][2], ds[2*kb+1][3], Pl[kb][3]);
        }

        // ---- O += P V ----
#pragma unroll
        for (int ntp = 0; ntp < 8; ntp++) {
            int hv = ntp * 16 + vh_sel;
            uint32_t vpan = ((hv >> 6) << 13);
            uint32_t vcol = (hv & 63) << 1;
#pragma unroll
            for (int kb = 0; kb < 4; kb++) {
                uint32_t addr = sb + 65536 + vpan +
                                SW128((kb * 16 + vrow_l) * 128 + vcol);
                uint32_t tH[4], tL[4];
                LDSM_X4_T(tH, addr);
                LDSM_X4_T(tL, addr + 16384);
                MMA16816(d_o[2*ntp],   Ph[kb], tH[0], tH[1]);
                MMA16816(d_o[2*ntp],   Pl[kb], tH[0], tH[1]);
                MMA16816(d_o[2*ntp],   Ph[kb], tL[0], tL[1]);
                MMA16816(d_o[2*ntp+1], Ph[kb], tH[2], tH[3]);
                MMA16816(d_o[2*ntp+1], Pl[kb], tH[2], tH[3]);
                MMA16816(d_o[2*ntp+1], Ph[kb], tL[2], tL[3]);
            }
        }
        __syncthreads();
    }

    // ---- epilogue: normalize, split, store ----
    float il0 = (l0 > 0.f) ? (1.f / l0) : 0.f;
    float il1 = (l1 > 0.f) ? (1.f / l1) : 0.f;
    size_t base0 = ((size_t)(b * Tt + qbase + r_lo))     * 2048 + n * 128;
    size_t base1 = ((size_t)(b * Tt + qbase + r_lo + 8)) * 2048 + n * 128;
#pragma unroll
    for (int nt = 0; nt < 16; nt++) {
        int h = nt * 8 + (lane & 3) * 2;
        uint32_t lop;
        uint32_t hip = split2(d_o[nt][0] * il0, d_o[nt][1] * il0, lop);
        *(uint32_t*)(g_atthi + base0 + h) = hip;
        *(uint32_t*)(g_attlo + base0 + h) = lop;
        hip = split2(d_o[nt][2] * il1, d_o[nt][3] * il1, lop);
        *(uint32_t*)(g_atthi + base1 + h) = hip;
        *(uint32_t*)(g_attlo + base1 + h) = lop;
    }
}

// ---------------------------------------------------------------------------
extern "C" void kernel_launch(void* const* d_in, const int* in_sizes, int n_in,
                              void* d_out, int out_size) {
    const float* x       = (const float*)d_in[0];
    const int*   seg     = (const int*)  d_in[1];
    const float* wq      = (const float*)d_in[2];
    const float* wk      = (const float*)d_in[3];
    const float* wv      = (const float*)d_in[4];
    const float* wo      = (const float*)d_in[5];
    const float* q_scale = (const float*)d_in[6];
    const float* k_scale = (const float*)d_in[7];
    float* out = (float*)d_out;

    float *qp, *kp, *vp;
    cudaGetSymbolAddress((void**)&qp, g_q);
    cudaGetSymbolAddress((void**)&kp, g_k);
    cudaGetSymbolAddress((void**)&vp, g_v);
    __nv_bfloat16 *xhi, *xlo, *ahi, *alo;
    __nv_bfloat16 *wqh, *wql, *wkh, *wkl, *wvh, *wvl, *woh, *wol;
    __nv_bfloat16 *qhh, *qhl, *khh, *khl;
    cudaGetSymbolAddress((void**)&xhi, g_xhi);
    cudaGetSymbolAddress((void**)&xlo, g_xlo);
    cudaGetSymbolAddress((void**)&ahi, g_atthi);
    cudaGetSymbolAddress((void**)&alo, g_attlo);
    cudaGetSymbolAddress((void**)&wqh, g_wqT_hi);
    cudaGetSymbolAddress((void**)&wql, g_wqT_lo);
    cudaGetSymbolAddress((void**)&wkh, g_wkT_hi);
    cudaGetSymbolAddress((void**)&wkl, g_wkT_lo);
    cudaGetSymbolAddress((void**)&wvh, g_wvT_hi);
    cudaGetSymbolAddress((void**)&wvl, g_wvT_lo);
    cudaGetSymbolAddress((void**)&woh, g_woT_hi);
    cudaGetSymbolAddress((void**)&wol, g_woT_lo);
    cudaGetSymbolAddress((void**)&qhh, g_qhh);
    cudaGetSymbolAddress((void**)&qhl, g_qhl);
    cudaGetSymbolAddress((void**)&khh, g_khh);
    cudaGetSymbolAddress((void**)&khl, g_khl);

    cudaFuncSetAttribute(gemm_hmma, cudaFuncAttributeMaxDynamicSharedMemorySize,
                         GEMM_SMEM);
    cudaFuncSetAttribute(attn_hmma, cudaFuncAttributeMaxDynamicSharedMemorySize,
                         ATT_SMEM);

    pos_kernel<<<Bb, 256>>>(seg);

    // split conversions
    conv_split<<<1024, 256>>>(x, xhi, xlo, (size_t)Mrows * Dd / 4);
    conv_tsplit<<<dim3(2048 / 32, 1024 / 32), dim3(32, 8)>>>(wq, wqh, wql, 1024, 2048);
    conv_tsplit<<<dim3(1024 / 32, 1024 / 32), dim3(32, 8)>>>(wk, wkh, wkl, 1024, 1024);
    conv_tsplit<<<dim3(1024 / 32, 1024 / 32), dim3(32, 8)>>>(wv, wvh, wvl, 1024, 1024);
    conv_tsplit<<<dim3(1024 / 32, 2048 / 32), dim3(32, 8)>>>(wo, woh, wol, 2048, 1024);

    // QKV projections (HMMA)
    gemm_hmma<<<dim3(2048 / 128, Mrows / 128), 256, GEMM_SMEM>>>(xhi, xlo, wqh, wql, qp, 2048, 1024);
    gemm_hmma<<<dim3(1024 / 128, Mrows / 128), 256, GEMM_SMEM>>>(xhi, xlo, wkh, wkl, kp, 1024, 1024);
    gemm_hmma<<<dim3(1024 / 128, Mrows / 128), 256, GEMM_SMEM>>>(xhi, xlo, wvh, wvl, vp, 1024, 1024);

    // RMSNorm + RoPE + split (q pre-scaled by SCALE)
    norm_rope_split<<<Mrows * Nn, 128>>>(qp, q_scale, qhh, qhl, Nn, SCALEf);
    norm_rope_split<<<Mrows * Kk, 128>>>(kp, k_scale, khh, khl, Kk, 1.0f);
    v_split<<<Mrows * Kk, 128>>>(vp);

    // HMMA flash attention (writes split bf16 att output)
    attn_hmma<<<dim3(Tt / 64, Nn, Bb), 128, ATT_SMEM>>>(seg);

    // output projection (HMMA)
    gemm_hmma<<<dim3(1024 / 128, Mrows / 128), 256, GEMM_SMEM>>>(ahi, alo, woh, wol, out, 1024, 2048);
}

// round 7
// speedup vs baseline: 4.4964x; 1.1554x over previous
#include <cuda_runtime.h>
#include <cuda_bf16.h>
#include <math.h>
#include <float.h>
#include <limits.h>
#include <stdint.h>

// Problem constants
#define Bb 2
#define Tt 2048
#define Dd 1024
#define Nn 16
#define Kk 8
#define Hh 128
#define Gg 2
#define Mrows (Bb*Tt)          // 4096

static constexpr float EPSf   = 1e-6f;
static constexpr float LOG_THETA = 13.815510557964274f;  // ln(1e6)
static constexpr float SCALEf = 0.08838834764831845f;    // 128^-0.5

// ---------------------------------------------------------------------------
// Scratch (allocation-free rule: __device__ globals)
// ---------------------------------------------------------------------------
__device__ float g_q[(size_t)Mrows * Nn * Hh];   // fp32 gemm out (pre-norm)
__device__ float g_k[(size_t)Mrows * Kk * Hh];
__device__ int   g_pos[Mrows];

// bf16 split buffers
__device__ __nv_bfloat16 g_xhi[(size_t)Mrows * Dd];
__device__ __nv_bfloat16 g_xlo[(size_t)Mrows * Dd];
__device__ __nv_bfloat16 g_atthi[(size_t)Mrows * Nn * Hh];   // attn out [row][n*H]
__device__ __nv_bfloat16 g_attlo[(size_t)Mrows * Nn * Hh];
__device__ __nv_bfloat16 g_wqT_hi[(size_t)(Nn*Hh) * Dd];
__device__ __nv_bfloat16 g_wqT_lo[(size_t)(Nn*Hh) * Dd];
__device__ __nv_bfloat16 g_wkT_hi[(size_t)(Kk*Hh) * Dd];
__device__ __nv_bfloat16 g_wkT_lo[(size_t)(Kk*Hh) * Dd];
__device__ __nv_bfloat16 g_wvT_hi[(size_t)(Kk*Hh) * Dd];
__device__ __nv_bfloat16 g_wvT_lo[(size_t)(Kk*Hh) * Dd];
__device__ __nv_bfloat16 g_woT_hi[(size_t)Dd * (Nn*Hh)];
__device__ __nv_bfloat16 g_woT_lo[(size_t)Dd * (Nn*Hh)];

// head-major bf16 split q/k/v for attention: [b][head][t][h]
__device__ __nv_bfloat16 g_qhh[(size_t)Bb * Nn * Tt * Hh];
__device__ __nv_bfloat16 g_qhl[(size_t)Bb * Nn * Tt * Hh];
__device__ __nv_bfloat16 g_khh[(size_t)Bb * Kk * Tt * Hh];
__device__ __nv_bfloat16 g_khl[(size_t)Bb * Kk * Tt * Hh];
__device__ __nv_bfloat16 g_vhh[(size_t)Bb * Kk * Tt * Hh];
__device__ __nv_bfloat16 g_vhl[(size_t)Bb * Kk * Tt * Hh];

// ---------------------------------------------------------------------------
// PTX helpers (sm_103 baseline ISA: cp.async, ldmatrix, mma.sync)
// ---------------------------------------------------------------------------
__device__ __forceinline__ uint32_t smem_u32(const void* p) {
    uint32_t a;
    asm("{ .reg .u64 t; cvta.to.shared.u64 t, %1; cvt.u32.u64 %0, t; }"
        : "=r"(a) : "l"(p));
    return a;
}
#define SW128(off) ((off) ^ (((off) >> 3) & 0x70))

#define CP_ASYNC16(saddr, gaddr) \
    asm volatile("cp.async.cg.shared.global [%0], [%1], 16;" \
        :: "r"(saddr), "l"(gaddr) : "memory")
#define CP_COMMIT() asm volatile("cp.async.commit_group;" ::: "memory")
#define CP_WAIT(n)  asm volatile("cp.async.wait_group %0;" :: "n"(n) : "memory")

#define LDSM_X4(r, addr) \
    asm volatile("ldmatrix.sync.aligned.m8n8.x4.shared.b16 {%0,%1,%2,%3}, [%4];" \
        : "=r"((r)[0]), "=r"((r)[1]), "=r"((r)[2]), "=r"((r)[3]) : "r"(addr))
#define LDSM_X4_T(r, addr) \
    asm volatile("ldmatrix.sync.aligned.m8n8.x4.trans.shared.b16 {%0,%1,%2,%3}, [%4];" \
        : "=r"((r)[0]), "=r"((r)[1]), "=r"((r)[2]), "=r"((r)[3]) : "r"(addr))

#define MMA16816(d, a, b0r, b1r) \
    asm volatile("mma.sync.aligned.m16n8k16.row.col.f32.bf16.bf16.f32 " \
        "{%0,%1,%2,%3}, {%4,%5,%6,%7}, {%8,%9}, {%0,%1,%2,%3};" \
        : "+f"((d)[0]), "+f"((d)[1]), "+f"((d)[2]), "+f"((d)[3]) \
        : "r"((a)[0]), "r"((a)[1]), "r"((a)[2]), "r"((a)[3]), \
          "r"((b0r)), "r"((b1r)))

// Split fp32 pair into packed bf16 hi + packed bf16 residual.
__device__ __forceinline__ uint32_t split2(float x0, float x1, uint32_t& lopack) {
    __nv_bfloat16 h0 = __float2bfloat16(x0), h1 = __float2bfloat16(x1);
    float r0 = x0 - __bfloat162float(h0), r1 = x1 - __bfloat162float(h1);
    __nv_bfloat16 g0 = __float2bfloat16(r0), g1 = __float2bfloat16(r1);
    lopack = (uint32_t)__bfloat16_as_ushort(g0) | ((uint32_t)__bfloat16_as_ushort(g1) << 16);
    return (uint32_t)__bfloat16_as_ushort(h0) | ((uint32_t)__bfloat16_as_ushort(h1) << 16);
}

// ---------------------------------------------------------------------------
// positions_from_segment_ids
// ---------------------------------------------------------------------------
__global__ void pos_kernel(const int* __restrict__ seg) {
    int b = blockIdx.x;
    int tid = threadIdx.x;
    __shared__ int sv[256], si[256];
    int bv = INT_MIN, bi = INT_MAX;
    for (int t = tid; t < Tt; t += 256) {
        int v = seg[b * Tt + t];
        if (v > bv) { bv = v; bi = t; }
    }
    sv[tid] = bv; si[tid] = bi;
    __syncthreads();
    for (int o = 128; o; o >>= 1) {
        if (tid < o) {
            if (sv[tid + o] > sv[tid] ||
                (sv[tid + o] == sv[tid] && si[tid + o] < si[tid])) {
                sv[tid] = sv[tid + o]; si[tid] = si[tid + o];
            }
        }
        __syncthreads();
    }
    int off = si[0];
    for (int t = tid; t < Tt; t += 256) {
        int v = seg[b * Tt + t];
        g_pos[b * Tt + t] = (v != 0) ? (t - off) : (1 << 30);
    }
}

// ---------------------------------------------------------------------------
// fp32 -> (hi, lo) bf16 split, elementwise
// ---------------------------------------------------------------------------
__global__ __launch_bounds__(256)
void conv_split(const float* __restrict__ src, __nv_bfloat16* __restrict__ hi,
                __nv_bfloat16* __restrict__ lo, size_t n4) {
    size_t i = (size_t)blockIdx.x * blockDim.x + threadIdx.x;
    size_t stride = (size_t)gridDim.x * blockDim.x;
    for (; i < n4; i += stride) {
        float4 v = ((const float4*)src)[i];
        uint32_t l01, l23;
        uint32_t h01 = split2(v.x, v.y, l01);
        uint32_t h23 = split2(v.z, v.w, l23);
        ((uint2*)hi)[i] = make_uint2(h01, h23);
        ((uint2*)lo)[i] = make_uint2(l01, l23);
    }
}

// ---------------------------------------------------------------------------
// Transpose + split: w[Kd, Nc] fp32 -> wT_hi/lo[Nc, Kd] bf16
// ---------------------------------------------------------------------------
__global__ __launch_bounds__(256)
void conv_tsplit(const float* __restrict__ w, __nv_bfloat16* __restrict__ hi,
                 __nv_bfloat16* __restrict__ lo, int Kd, int Nc) {
    __shared__ float t[32][33];
    int n0 = blockIdx.x * 32, k0 = blockIdx.y * 32;
    int tx = threadIdx.x, ty = threadIdx.y;
    for (int i = ty; i < 32; i += 8)
        t[i][tx] = w[(size_t)(k0 + i) * Nc + n0 + tx];
    __syncthreads();
    for (int i = ty; i < 32; i += 8) {
        float v = t[tx][i];
        __nv_bfloat16 h = __float2bfloat16(v);
        __nv_bfloat16 l = __float2bfloat16(v - __bfloat162float(h));
        size_t o = (size_t)(n0 + i) * Kd + k0 + tx;
        hi[o] = h; lo[o] = l;
    }
}

// ---------------------------------------------------------------------------
// HMMA (mma.sync) bf16-split GEMM: C[M,Nc] = A[M,Kd] x Bt[Nc,Kd]^T
// vmode=1: write result as bf16 hi/lo split, head-major for V.
// ---------------------------------------------------------------------------
#define GSTAGE 65536
#define GEMM_SMEM (2 * GSTAGE)

__global__ __launch_bounds__(256)
void gemm_hmma(const __nv_bfloat16* __restrict__ Ahi, const __nv_bfloat16* __restrict__ Alo,
               const __nv_bfloat16* __restrict__ Bhi, const __nv_bfloat16* __restrict__ Blo,
               float* __restrict__ C,
               __nv_bfloat16* __restrict__ Vh, __nv_bfloat16* __restrict__ Vl, int vmode,
               int Nc, int Kd) {
    extern __shared__ char smc[];
    const int tid  = threadIdx.x;
    const int lane = tid & 31;
    const int wid  = tid >> 5;
    const int warp_m = wid & 3;
    const int warp_n = wid >> 2;
    const int m0 = blockIdx.y * 128, n0 = blockIdx.x * 128;

    const int u = tid & 7;
    const int r = tid >> 3;

    const uint32_t sbase = smem_u32(smc);
    const int nchunk = Kd >> 6;

    float d[2][8][4];
#pragma unroll
    for (int mt = 0; mt < 2; mt++)
#pragma unroll
        for (int nt = 0; nt < 8; nt++)
#pragma unroll
            for (int j = 0; j < 4; j++) d[mt][nt][j] = 0.f;

#define ISSUE_CHUNK(c, s) do {                                               \
    const int k0e = (c) * 64;                                                \
    char* buf = smc + (s) * GSTAGE;                                          \
    _Pragma("unroll")                                                        \
    for (int i = 0; i < 4; i++) {                                            \
        int row = r + i * 32;                                                \
        uint32_t so = SW128(row * 128 + u * 16);                             \
        uint32_t sa = smem_u32(buf) + so;                                    \
        const __nv_bfloat16* pa_hi = Ahi + (size_t)(m0 + row) * Kd + k0e + u * 8; \
        const __nv_bfloat16* pa_lo = Alo + (size_t)(m0 + row) * Kd + k0e + u * 8; \
        const __nv_bfloat16* pb_hi = Bhi + (size_t)(n0 + row) * Kd + k0e + u * 8; \
        const __nv_bfloat16* pb_lo = Blo + (size_t)(n0 + row) * Kd + k0e + u * 8; \
        CP_ASYNC16(sa,         pa_hi);                                       \
        CP_ASYNC16(sa + 16384, pa_lo);                                       \
        CP_ASYNC16(sa + 32768, pb_hi);                                       \
        CP_ASYNC16(sa + 49152, pb_lo);                                       \
    }                                                                        \
} while (0)

    ISSUE_CHUNK(0, 0);
    CP_COMMIT();

    for (int c = 0; c < nchunk; c++) {
        if (c + 1 < nchunk) { ISSUE_CHUNK(c + 1, (c + 1) & 1); CP_COMMIT(); CP_WAIT(1); }
        else                { CP_WAIT(0); }
        __syncthreads();

        const uint32_t sb = sbase + (c & 1) * GSTAGE;
#pragma unroll
        for (int s = 0; s < 4; s++) {
            uint32_t aH[2][4], aL[2][4];
#pragma unroll
            for (int mt = 0; mt < 2; mt++) {
                int row  = warp_m * 32 + mt * 16 + (lane & 7) + ((lane >> 3) & 1) * 8;
                int unit = s * 2 + (lane >> 4);
                uint32_t addr = sb + SW128(row * 128 + unit * 16);
                LDSM_X4(aH[mt], addr);
                LDSM_X4(aL[mt], addr + 16384);
            }
            uint32_t bH[8][2], bL[8][2];
#pragma unroll
            for (int np = 0; np < 4; np++) {
                int row  = warp_n * 64 + np * 16 + ((lane >> 4) & 1) * 8 + (lane & 7);
                int unit = s * 2 + ((lane >> 3) & 1);
                uint32_t addr = sb + 32768 + SW128(row * 128 + unit * 16);
                uint32_t tmp[4];
                LDSM_X4(tmp, addr);
                bH[2*np][0] = tmp[0]; bH[2*np][1] = tmp[1];
                bH[2*np+1][0] = tmp[2]; bH[2*np+1][1] = tmp[3];
                LDSM_X4(tmp, addr + 16384);
                bL[2*np][0] = tmp[0]; bL[2*np][1] = tmp[1];
                bL[2*np+1][0] = tmp[2]; bL[2*np+1][1] = tmp[3];
            }
#pragma unroll
            for (int mt = 0; mt < 2; mt++)
#pragma unroll
                for (int nt = 0; nt < 8; nt++) {
                    MMA16816(d[mt][nt], aH[mt], bH[nt][0], bH[nt][1]);
                    MMA16816(d[mt][nt], aH[mt], bL[nt][0], bL[nt][1]);
                    MMA16816(d[mt][nt], aL[mt], bH[nt][0], bH[nt][1]);
                }
        }
        __syncthreads();
    }

    if (!vmode) {
#pragma unroll
        for (int mt = 0; mt < 2; mt++) {
#pragma unroll
            for (int nt = 0; nt < 8; nt++) {
                int row = m0 + warp_m * 32 + mt * 16 + (lane >> 2);
                int col = n0 + warp_n * 64 + nt * 8 + (lane & 3) * 2;
                *(float2*)&C[(size_t)row * Nc + col] =
                    make_float2(d[mt][nt][0], d[mt][nt][1]);
                *(float2*)&C[(size_t)(row + 8) * Nc + col] =
                    make_float2(d[mt][nt][2], d[mt][nt][3]);
            }
        }
    } else {
        // head-major split store for V: row = b*2048+t, col = kv*128+h
#pragma unroll
        for (int mt = 0; mt < 2; mt++) {
#pragma unroll
            for (int nt = 0; nt < 8; nt++) {
                int row = m0 + warp_m * 32 + mt * 16 + (lane >> 2);
                int col = n0 + warp_n * 64 + nt * 8 + (lane & 3) * 2;
                int bq = row >> 11, t = row & 2047;
                int kv = col >> 7, h = col & 127;
                size_t o0 = ((size_t)(bq * Kk + kv) * Tt + t) * Hh + h;
                size_t o1 = ((size_t)(bq * Kk + kv) * Tt + t + 8) * Hh + h;
                uint32_t lop;
                uint32_t hip = split2(d[mt][nt][0], d[mt][nt][1], lop);
                *(uint32_t*)(Vh + o0) = hip;
                *(uint32_t*)(Vl + o0) = lop;
                hip = split2(d[mt][nt][2], d[mt][nt][3], lop);
                *(uint32_t*)(Vh + o1) = hip;
                *(uint32_t*)(Vl + o1) = lop;
            }
        }
    }
#undef ISSUE_CHUNK
}

// ---------------------------------------------------------------------------
// Fused RMSNorm + RoPE + bf16 split + head-major store.
// ---------------------------------------------------------------------------
__global__ __launch_bounds__(128)
void norm_rope_split(const float* __restrict__ in, const float* __restrict__ scale,
                     __nv_bfloat16* __restrict__ outhi, __nv_bfloat16* __restrict__ outlo,
                     int heads, float post_scale) {
    const int row  = blockIdx.x;
    const int h    = threadIdx.x;
    const int trow = row / heads;
    const int n    = row - trow * heads;
    const int b    = trow >> 11;
    const int t    = trow & 2047;

    float v = in[(size_t)row * Hh + h];
    float ss = v * v;
#pragma unroll
    for (int o = 16; o; o >>= 1) ss += __shfl_xor_sync(0xffffffffu, ss, o);
    __shared__ float warpsum[4];
    __shared__ float s_n[Hh];
    if ((h & 31) == 0) warpsum[h >> 5] = ss;
    __syncthreads();
    float total = warpsum[0] + warpsum[1] + warpsum[2] + warpsum[3];
    float inv_rms = rsqrtf(total * (1.0f / 128.0f) + EPSf);
    s_n[h] = v * inv_rms * scale[h];
    __syncthreads();

    int pos = g_pos[trow];
    int i = h & 63;
    float inv_freq = __expf(-(float)i * (LOG_THETA / 64.0f));
    float ang = (float)pos * inv_freq;
    float sn = sinf(ang), cs = cosf(ang);
    float out = (h < 64) ? (s_n[h] * cs - s_n[h + 64] * sn)
                         : (s_n[h] * cs + s_n[h - 64] * sn);
    out *= post_scale;
    __nv_bfloat16 hi = __float2bfloat16(out);
    __nv_bfloat16 lo = __float2bfloat16(out - __bfloat162float(hi));
    size_t o = ((size_t)(b * heads + n) * Tt + t) * Hh + h;
    outhi[o] = hi;
    outlo[o] = lo;
}

// ---------------------------------------------------------------------------
// HMMA flash attention, GQA-paired: one CTA serves BOTH q-heads of a kv-head.
// 256 threads: warps 0-3 -> head 2*kvh, warps 4-7 -> head 2*kvh+1.
// cp.async double-buffered KV over precomputed active-tile list.
// smem layout (bytes):
//   0      : Q tiles, 2 heads x (hi 16K + lo 16K) = 64K
//   65536  : KV stage 0 (khi 16K, klo 16K, vhi 16K, vlo 16K) = 64K
//   131072 : KV stage 1 = 64K
//   196608 : pos[2048] (8K)
//   204800 : seg[2048] (8K)
//   212992 : kmin[32], tiles[32], ctl[2]
// ---------------------------------------------------------------------------
#define AT_ST0  65536
#define AT_POS  196608
#define AT_SEG  204800
#define AT_META 212992
#define ATT_SMEM (212992 + 512)

__global__ __launch_bounds__(256)
void attn_hmma(const int* __restrict__ seg_g) {
    extern __shared__ char sm[];
    const uint32_t sb = smem_u32(sm);
    int* sPos  = (int*)(sm + AT_POS);
    int* sSeg  = (int*)(sm + AT_SEG);
    int* sKmin = (int*)(sm + AT_META);
    int* sTiles = sKmin + 32;
    int* sCtl   = sTiles + 32;

    const int tid = threadIdx.x, lane = tid & 31, warp = tid >> 5;
    const int qbase = blockIdx.x * 64;
    const int kvh = blockIdx.y, b = blockIdx.z;
    const int hsel = warp >> 2;            // which q-head of the pair
    const int mwarp = warp & 3;
    const int n = kvh * 2 + hsel;

    // ---- prologue loads: pos/seg (whole sequence) + Q tiles (both heads) ----
    for (int i = tid; i < 2048; i += 256) {
        sPos[i] = g_pos[b * Tt + i];
        sSeg[i] = seg_g[b * Tt + i];
    }
    for (int i = tid; i < 2048; i += 256) {
        int hh = i >> 10;
        int j = i & 1023;
        int r = j >> 4, u = j & 15;
        uint32_t off = hh * 32768 + ((u >> 3) << 13) + SW128(r * 128 + (u & 7) * 16);
        const char* qh = (const char*)(g_qhh + ((size_t)(b * Nn + kvh * 2 + hh) * Tt + qbase) * Hh);
        const char* ql = (const char*)(g_qhl + ((size_t)(b * Nn + kvh * 2 + hh) * Tt + qbase) * Hh);
        *(uint4*)(sm + off)         = *(const uint4*)(qh + r * 256 + u * 16);
        *(uint4*)(sm + 16384 + off) = *(const uint4*)(ql + r * 256 + u * 16);
    }
    __syncthreads();

    // per-tile kmin (warp w -> tiles 4w..4w+3), qmax (warp 0)
    {
#pragma unroll
        for (int j = 0; j < 4; j++) {
            int tt = warp * 4 + j;
            int mn = min(sPos[tt * 64 + lane], sPos[tt * 64 + 32 + lane]);
#pragma unroll
            for (int o = 16; o; o >>= 1) mn = min(mn, __shfl_xor_sync(0xffffffffu, mn, o));
            if (lane == 0) sKmin[tt] = mn;
        }
        if (warp == 0) {
            int v = max(sPos[qbase + lane], sPos[qbase + 32 + lane]);
#pragma unroll
            for (int o = 16; o; o >>= 1) v = max(v, __shfl_xor_sync(0xffffffffu, v, o));
            if (lane == 0) sCtl[0] = v;
        }
    }
    __syncthreads();
    if (tid == 0) {
        int qmax = sCtl[0], na = 0;
        for (int tt = 0; tt < 32; tt++)
            if (sKmin[tt] <= qmax) sTiles[na++] = tt;
        sCtl[1] = na;
    }
    __syncthreads();
    const int nactive = sCtl[1];

    const char* kh = (const char*)(g_khh + ((size_t)(b * Kk + kvh) * Tt) * Hh);
    const char* kl = (const char*)(g_khl + ((size_t)(b * Kk + kvh) * Tt) * Hh);
    const char* vh = (const char*)(g_vhh + ((size_t)(b * Kk + kvh) * Tt) * Hh);
    const char* vl = (const char*)(g_vhl + ((size_t)(b * Kk + kvh) * Tt) * Hh);

#define AT_ISSUE(tt, st) do {                                                \
    const int sbase_ = (tt) * 64;                                            \
    uint32_t stb = sb + AT_ST0 + (st) * 65536;                               \
    for (int i = tid; i < 1024; i += 256) {                                  \
        int r = i >> 4, u = i & 15;                                          \
        uint32_t off = ((u >> 3) << 13) + SW128(r * 128 + (u & 7) * 16);     \
        size_t go = (size_t)(sbase_ + r) * 256 + u * 16;                     \
        CP_ASYNC16(stb + off,         kh + go);                              \
        CP_ASYNC16(stb + 16384 + off, kl + go);                              \
        CP_ASYNC16(stb + 32768 + off, vh + go);                              \
        CP_ASYNC16(stb + 49152 + off, vl + go);                              \
    }                                                                        \
} while (0)

    // per-lane q row info
    const int r_lo = mwarp * 16 + (lane >> 2);
    const int qp0 = sPos[qbase + r_lo];
    const int qp1 = sPos[qbase + r_lo + 8];
    const int qs0 = sSeg[qbase + r_lo];
    const int qs1 = sSeg[qbase + r_lo + 8];

    float d_o[16][4];
#pragma unroll
    for (int nt = 0; nt < 16; nt++)
#pragma unroll
        for (int j = 0; j < 4; j++) d_o[nt][j] = 0.f;
    float m0 = -1e30f, m1 = -1e30f, l0 = 0.f, l1 = 0.f;

    // fragment address components
    const int qrow_l = mwarp * 16 + (lane & 7) + ((lane >> 3) & 1) * 8;
    const int krow_l = ((lane >> 4) & 1) * 8 + (lane & 7);
    const int vrow_l = (((lane >> 3) & 1) << 3) + (lane & 7);
    const int qh_sel = (lane >> 4) << 3;
    const int kh_sel = ((lane >> 3) & 1) << 3;
    const int vh_sel = (lane >> 4) << 3;
    const uint32_t qpanel = sb + hsel * 32768;

    if (nactive > 0) { AT_ISSUE(sTiles[0], 0); CP_COMMIT(); }

    for (int j = 0; j < nactive; j++) {
        const int tt = sTiles[j];
        const int sbase = tt * 64;
        if (j + 1 < nactive) { AT_ISSUE(sTiles[j + 1], (j + 1) & 1); CP_COMMIT(); CP_WAIT(1); }
        else                 { CP_WAIT(0); }
        __syncthreads();

        const uint32_t stb = sb + AT_ST0 + (j & 1) * 65536;

        // ---- S = Q K^T (16 x 64 per warp) ----
        float ds[8][4];
#pragma unroll
        for (int nt = 0; nt < 8; nt++)
#pragma unroll
            for (int jj = 0; jj < 4; jj++) ds[nt][jj] = 0.f;

#pragma unroll
        for (int ks = 0; ks < 8; ks++) {
            int hq = ks * 16 + qh_sel;
            uint32_t qoff = ((hq >> 6) << 13) + SW128(qrow_l * 128 + ((hq & 63) << 1));
            uint32_t aH[4], aL[4];
            LDSM_X4(aH, qpanel + qoff);
            LDSM_X4(aL, qpanel + 16384 + qoff);
            int hk = ks * 16 + kh_sel;
            uint32_t kpan = ((hk >> 6) << 13);
            uint32_t kcol = (hk & 63) << 1;
#pragma unroll
            for (int np = 0; np < 4; np++) {
                uint32_t addr = stb + kpan + SW128((np * 16 + krow_l) * 128 + kcol);
                uint32_t tH[4], tL[4];
                LDSM_X4(tH, addr);
                LDSM_X4(tL, addr + 16384);
                MMA16816(ds[2*np],   aH, tH[0], tH[1]);
                MMA16816(ds[2*np],   aH, tL[0], tL[1]);
                MMA16816(ds[2*np],   aL, tH[0], tH[1]);
                MMA16816(ds[2*np+1], aH, tH[2], tH[3]);
                MMA16816(ds[2*np+1], aH, tL[2], tL[3]);
                MMA16816(ds[2*np+1], aL, tH[2], tH[3]);
            }
        }

        // ---- mask ----
#pragma unroll
        for (int nt = 0; nt < 8; nt++) {
            int c = sbase + nt * 8 + (lane & 3) * 2;
            int kp0 = sPos[c], kp1 = sPos[c + 1];
            int ks0 = sSeg[c], ks1 = sSeg[c + 1];
            if (!(kp0 <= qp0 && ks0 == qs0)) ds[nt][0] = -1e30f;
            if (!(kp1 <= qp0 && ks1 == qs0)) ds[nt][1] = -1e30f;
            if (!(kp0 <= qp1 && ks0 == qs1)) ds[nt][2] = -1e30f;
            if (!(kp1 <= qp1 && ks1 == qs1)) ds[nt][3] = -1e30f;
        }

        // ---- online softmax ----
        float tm0 = -1e30f, tm1 = -1e30f;
#pragma unroll
        for (int nt = 0; nt < 8; nt++) {
            tm0 = fmaxf(tm0, fmaxf(ds[nt][0], ds[nt][1]));
            tm1 = fmaxf(tm1, fmaxf(ds[nt][2], ds[nt][3]));
        }
        tm0 = fmaxf(tm0, __shfl_xor_sync(0xffffffffu, tm0, 1));
        tm0 = fmaxf(tm0, __shfl_xor_sync(0xffffffffu, tm0, 2));
        tm1 = fmaxf(tm1, __shfl_xor_sync(0xffffffffu, tm1, 1));
        tm1 = fmaxf(tm1, __shfl_xor_sync(0xffffffffu, tm1, 2));
        float nm0 = fmaxf(m0, tm0), nm1 = fmaxf(m1, tm1);
        float a0 = __expf(m0 - nm0), a1 = __expf(m1 - nm1);
        float gg0 = (nm0 > -0.9e30f) ? 1.f : 0.f;
        float gg1 = (nm1 > -0.9e30f) ? 1.f : 0.f;
        float s0 = 0.f, s1 = 0.f;
#pragma unroll
        for (int nt = 0; nt < 8; nt++) {
            ds[nt][0] = gg0 * __expf(ds[nt][0] - nm0);
            ds[nt][1] = gg0 * __expf(ds[nt][1] - nm0);
            ds[nt][2] = gg1 * __expf(ds[nt][2] - nm1);
            ds[nt][3] = gg1 * __expf(ds[nt][3] - nm1);
            s0 += ds[nt][0] + ds[nt][1];
            s1 += ds[nt][2] + ds[nt][3];
        }
        s0 += __shfl_xor_sync(0xffffffffu, s0, 1);
        s0 += __shfl_xor_sync(0xffffffffu, s0, 2);
        s1 += __shfl_xor_sync(0xffffffffu, s1, 1);
        s1 += __shfl_xor_sync(0xffffffffu, s1, 2);
        l0 = l0 * a0 + s0; m0 = nm0;
        l1 = l1 * a1 + s1; m1 = nm1;
#pragma unroll
        for (int nt = 0; nt < 16; nt++) {
            d_o[nt][0] *= a0; d_o[nt][1] *= a0;
            d_o[nt][2] *= a1; d_o[nt][3] *= a1;
        }

        // ---- pack P into hi/lo A-fragments ----
        uint32_t Ph[4][4], Pl[4][4];
#pragma unroll
        for (int kb = 0; kb < 4; kb++) {
            Ph[kb][0] = split2(ds[2*kb][0],   ds[2*kb][1],   Pl[kb][0]);
            Ph[kb][1] = split2(ds[2*kb][2],   ds[2*kb][3],   Pl[kb][1]);
            Ph[kb][2] = split2(ds[2*kb+1][0], ds[2*kb+1][1], Pl[kb][2]);
            Ph[kb][3] = split2(ds[2*kb+1][2], ds[2*kb+1][3], Pl[kb][3]);
        }

        // ---- O += P V ----
#pragma unroll
        for (int ntp = 0; ntp < 8; ntp++) {
            int hv = ntp * 16 + vh_sel;
            uint32_t vpan = ((hv >> 6) << 13);
            uint32_t vcol = (hv & 63) << 1;
#pragma unroll
            for (int kb = 0; kb < 4; kb++) {
                uint32_t addr = stb + 32768 + vpan + SW128((kb * 16 + vrow_l) * 128 + vcol);
                uint32_t tH[4], tL[4];
                LDSM_X4_T(tH, addr);
                LDSM_X4_T(tL, addr + 16384);
                MMA16816(d_o[2*ntp],   Ph[kb], tH[0], tH[1]);
                MMA16816(d_o[2*ntp],   Pl[kb], tH[0], tH[1]);
                MMA16816(d_o[2*ntp],   Ph[kb], tL[0], tL[1]);
                MMA16816(d_o[2*ntp+1], Ph[kb], tH[2], tH[3]);
                MMA16816(d_o[2*ntp+1], Pl[kb], tH[2], tH[3]);
                MMA16816(d_o[2*ntp+1], Ph[kb], tL[2], tL[3]);
            }
        }
        __syncthreads();
    }
#undef AT_ISSUE

    // ---- epilogue: normalize, split, store ----
    float il0 = (l0 > 0.f) ? (1.f / l0) : 0.f;
    float il1 = (l1 > 0.f) ? (1.f / l1) : 0.f;
    size_t base0 = ((size_t)(b * Tt + qbase + r_lo))     * 2048 + n * 128;
    size_t base1 = ((size_t)(b * Tt + qbase + r_lo + 8)) * 2048 + n * 128;
#pragma unroll
    for (int nt = 0; nt < 16; nt++) {
        int h = nt * 8 + (lane & 3) * 2;
        uint32_t lop;
        uint32_t hip = split2(d_o[nt][0] * il0, d_o[nt][1] * il0, lop);
        *(uint32_t*)(g_atthi + base0 + h) = hip;
        *(uint32_t*)(g_attlo + base0 + h) = lop;
        hip = split2(d_o[nt][2] * il1, d_o[nt][3] * il1, lop);
        *(uint32_t*)(g_atthi + base1 + h) = hip;
        *(uint32_t*)(g_attlo + base1 + h) = lop;
    }
}

// ---------------------------------------------------------------------------
extern "C" void kernel_launch(void* const* d_in, const int* in_sizes, int n_in,
                              void* d_out, int out_size) {
    const float* x       = (const float*)d_in[0];
    const int*   seg     = (const int*)  d_in[1];
    const float* wq      = (const float*)d_in[2];
    const float* wk      = (const float*)d_in[3];
    const float* wv      = (const float*)d_in[4];
    const float* wo      = (const float*)d_in[5];
    const float* q_scale = (const float*)d_in[6];
    const float* k_scale = (const float*)d_in[7];
    float* out = (float*)d_out;

    float *qp, *kp;
    cudaGetSymbolAddress((void**)&qp, g_q);
    cudaGetSymbolAddress((void**)&kp, g_k);
    __nv_bfloat16 *xhi, *xlo, *ahi, *alo;
    __nv_bfloat16 *wqh, *wql, *wkh, *wkl, *wvh, *wvl, *woh, *wol;
    __nv_bfloat16 *qhh, *qhl, *khh, *khl, *vhh, *vhl;
    cudaGetSymbolAddress((void**)&xhi, g_xhi);
    cudaGetSymbolAddress((void**)&xlo, g_xlo);
    cudaGetSymbolAddress((void**)&ahi, g_atthi);
    cudaGetSymbolAddress((void**)&alo, g_attlo);
    cudaGetSymbolAddress((void**)&wqh, g_wqT_hi);
    cudaGetSymbolAddress((void**)&wql, g_wqT_lo);
    cudaGetSymbolAddress((void**)&wkh, g_wkT_hi);
    cudaGetSymbolAddress((void**)&wkl, g_wkT_lo);
    cudaGetSymbolAddress((void**)&wvh, g_wvT_hi);
    cudaGetSymbolAddress((void**)&wvl, g_wvT_lo);
    cudaGetSymbolAddress((void**)&woh, g_woT_hi);
    cudaGetSymbolAddress((void**)&wol, g_woT_lo);
    cudaGetSymbolAddress((void**)&qhh, g_qhh);
    cudaGetSymbolAddress((void**)&qhl, g_qhl);
    cudaGetSymbolAddress((void**)&khh, g_khh);
    cudaGetSymbolAddress((void**)&khl, g_khl);
    cudaGetSymbolAddress((void**)&vhh, g_vhh);
    cudaGetSymbolAddress((void**)&vhl, g_vhl);

    cudaFuncSetAttribute(gemm_hmma, cudaFuncAttributeMaxDynamicSharedMemorySize,
                         GEMM_SMEM);
    cudaFuncSetAttribute(attn_hmma, cudaFuncAttributeMaxDynamicSharedMemorySize,
                         ATT_SMEM);

    pos_kernel<<<Bb, 256>>>(seg);

    // split conversions
    conv_split<<<1024, 256>>>(x, xhi, xlo, (size_t)Mrows * Dd / 4);
    conv_tsplit<<<dim3(2048 / 32, 1024 / 32), dim3(32, 8)>>>(wq, wqh, wql, 1024, 2048);
    conv_tsplit<<<dim3(1024 / 32, 1024 / 32), dim3(32, 8)>>>(wk, wkh, wkl, 1024, 1024);
    conv_tsplit<<<dim3(1024 / 32, 1024 / 32), dim3(32, 8)>>>(wv, wvh, wvl, 1024, 1024);
    conv_tsplit<<<dim3(1024 / 32, 2048 / 32), dim3(32, 8)>>>(wo, woh, wol, 2048, 1024);

    // QKV projections (HMMA); V writes head-major bf16 split directly
    gemm_hmma<<<dim3(2048 / 128, Mrows / 128), 256, GEMM_SMEM>>>(
        xhi, xlo, wqh, wql, qp, ((__nv_bfloat16*)0), ((__nv_bfloat16*)0), 0, 2048, 1024);
    gemm_hmma<<<dim3(1024 / 128, Mrows / 128), 256, GEMM_SMEM>>>(
        xhi, xlo, wkh, wkl, kp, ((__nv_bfloat16*)0), ((__nv_bfloat16*)0), 0, 1024, 1024);
    gemm_hmma<<<dim3(1024 / 128, Mrows / 128), 256, GEMM_SMEM>>>(
        xhi, xlo, wvh, wvl, (float*)0, vhh, vhl, 1, 1024, 1024);

    // RMSNorm + RoPE + split (q pre-scaled by SCALE)
    norm_rope_split<<<Mrows * Nn, 128>>>(qp, q_scale, qhh, qhl, Nn, SCALEf);
    norm_rope_split<<<Mrows * Kk, 128>>>(kp, k_scale, khh, khl, Kk, 1.0f);

    // HMMA flash attention (GQA-paired, cp.async pipelined)
    attn_hmma<<<dim3(Tt / 64, Kk, Bb), 256, ATT_SMEM>>>(seg);

    // output projection (HMMA)
    gemm_hmma<<<dim3(1024 / 128, Mrows / 128), 256, GEMM_SMEM>>>(
        ahi, alo, woh, wol, out, ((__nv_bfloat16*)0), ((__nv_bfloat16*)0), 0, 1024, 2048);
}